// round 1
// baseline (speedup 1.0000x reference)
#include <cuda_runtime.h>

#define BATCH 16
#define NNODE 1024
#define DIM 256
#define HEADS 4
#define HC 64
#define NBR 1023
#define TSTEPS 20

// ---------------- scratch (device globals; no allocation allowed) ----------------
__device__ float g_h0[BATCH * NNODE * DIM];
__device__ float g_h1[BATCH * NNODE * DIM];
__device__ float g_wh[BATCH * NNODE * DIM];
__device__ float g_pos[BATCH * NNODE * 2];
__device__ float g_as[BATCH * HEADS * NNODE];
__device__ float g_ad[BATCH * HEADS * NNODE];
__device__ float g_asmax[BATCH * HEADS];

// ---------------- embed: feature extract + (5->256) matmul + relu + LN ----------------
__global__ __launch_bounds__(256) void embed_kernel(
    const float* __restrict__ ego, const float* __restrict__ nbr,
    const float* __restrict__ node_w, const float* __restrict__ node_b,
    const float* __restrict__ node_g, const float* __restrict__ node_bb,
    const float* __restrict__ ego_w, const float* __restrict__ ego_b,
    const float* __restrict__ ego_g, const float* __restrict__ ego_bb)
{
    int bn = blockIdx.x;
    int b = bn >> 10, n = bn & 1023;
    int t = threadIdx.x;
    __shared__ float f[5];
    __shared__ float ws[8], wq[8];
    if (t < 5) {
        float v = (n == 0) ? ego[(b * TSTEPS + TSTEPS - 1) * 7 + t]
                           : nbr[((b * NBR + (n - 1)) * TSTEPS + TSTEPS - 1) * 11 + t];
        f[t] = v;
        if (t < 2) g_pos[bn * 2 + t] = v;
    }
    __syncthreads();
    const float *W, *bi, *g, *bb;
    if (n == 0) { W = ego_w;  bi = ego_b;  g = ego_g;  bb = ego_bb; }
    else        { W = node_w; bi = node_b; g = node_g; bb = node_bb; }
    float v = bi[t];
#pragma unroll
    for (int k = 0; k < 5; k++) v = fmaf(f[k], W[k * DIM + t], v);
    v = fmaxf(v, 0.f);
    // LayerNorm over 256 (one value per thread)
    float s = v, q = v * v;
#pragma unroll
    for (int o = 16; o; o >>= 1) {
        s += __shfl_down_sync(0xffffffffu, s, o);
        q += __shfl_down_sync(0xffffffffu, q, o);
    }
    int lane = t & 31, w = t >> 5;
    if (lane == 0) { ws[w] = s; wq[w] = q; }
    __syncthreads();
    float sum = 0.f, sq = 0.f;
#pragma unroll
    for (int i = 0; i < 8; i++) { sum += ws[i]; sq += wq[i]; }
    float mean = sum * (1.f / 256.f);
    float var = fmaxf(sq * (1.f / 256.f) - mean * mean, 0.f);
    float inv = rsqrtf(var + 1e-5f);
    g_h0[bn * DIM + t] = (v - mean) * inv * g[t] + bb[t];
}

// ---------------- SGEMM: C[M,256] = A[M,256] @ W[256,256] (+bias) ----------------
// 128x128 block tile, BK=8, 8x8 per-thread micro-tile, 256 threads.
template <bool BIAS>
__global__ __launch_bounds__(256) void sgemm256(
    const float* __restrict__ A, const float* __restrict__ W,
    const float* __restrict__ bias, float* __restrict__ C)
{
    __shared__ float As[8][128];
    __shared__ float Bs[8][128];
    int tid = threadIdx.x;
    int m0 = blockIdx.x * 128, n0 = blockIdx.y * 128;
    int tx = tid & 15, ty = tid >> 4;
    int arow = tid >> 1, ac = (tid & 1) * 4;
    int brow = tid >> 5, bc = (tid & 31) * 4;
    const float* Ag = A + (m0 + arow) * 256 + ac;
    const float* Wg = W + brow * 256 + n0 + bc;
    float acc[8][8] = {};
    float4 a4 = *(const float4*)Ag;
    float4 b4 = *(const float4*)Wg;
    for (int kt = 0; kt < 32; kt++) {
        As[ac + 0][arow] = a4.x; As[ac + 1][arow] = a4.y;
        As[ac + 2][arow] = a4.z; As[ac + 3][arow] = a4.w;
        *(float4*)&Bs[brow][bc] = b4;
        __syncthreads();
        if (kt < 31) {
            a4 = *(const float4*)(Ag + (kt + 1) * 8);
            b4 = *(const float4*)(Wg + (kt + 1) * 8 * 256);
        }
#pragma unroll
        for (int k = 0; k < 8; k++) {
            float av[8], bv[8];
            *(float4*)&av[0] = *(const float4*)&As[k][ty * 8];
            *(float4*)&av[4] = *(const float4*)&As[k][ty * 8 + 4];
            *(float4*)&bv[0] = *(const float4*)&Bs[k][tx * 8];
            *(float4*)&bv[4] = *(const float4*)&Bs[k][tx * 8 + 4];
#pragma unroll
            for (int i = 0; i < 8; i++)
#pragma unroll
                for (int j = 0; j < 8; j++)
                    acc[i][j] = fmaf(av[i], bv[j], acc[i][j]);
        }
        __syncthreads();
    }
#pragma unroll
    for (int i = 0; i < 8; i++) {
        int row = m0 + ty * 8 + i;
#pragma unroll
        for (int j = 0; j < 8; j += 4) {
            float4 o = make_float4(acc[i][j], acc[i][j + 1], acc[i][j + 2], acc[i][j + 3]);
            if (BIAS) {
                float4 bv = *(const float4*)(bias + n0 + tx * 8 + j);
                o.x += bv.x; o.y += bv.y; o.z += bv.z; o.w += bv.w;
            }
            *(float4*)&C[row * 256 + n0 + tx * 8 + j] = o;
        }
    }
}

// ---------------- a_src / a_dst per (b,n,h): dot(wh_head, a_vec) ----------------
__global__ __launch_bounds__(256) void sad_kernel(
    const float* __restrict__ wh,
    const float* __restrict__ asrc, const float* __restrict__ adst)
{
    int gw = (blockIdx.x * 256 + threadIdx.x) >> 5;
    int lane = threadIdx.x & 31;
    if (gw >= BATCH * NNODE) return;
    int b = gw >> 10, n = gw & 1023;
    const float* row = wh + (long long)gw * DIM;
#pragma unroll
    for (int h = 0; h < HEADS; h++) {
        float x0 = row[h * 64 + lane], x1 = row[h * 64 + 32 + lane];
        float s = x0 * asrc[h * 64 + lane] + x1 * asrc[h * 64 + 32 + lane];
        float d = x0 * adst[h * 64 + lane] + x1 * adst[h * 64 + 32 + lane];
#pragma unroll
        for (int o = 16; o; o >>= 1) {
            s += __shfl_down_sync(0xffffffffu, s, o);
            d += __shfl_down_sync(0xffffffffu, d, o);
        }
        if (lane == 0) {
            g_as[(b * HEADS + h) * NNODE + n] = s;
            g_ad[(b * HEADS + h) * NNODE + n] = d;
        }
    }
}

// ---------------- max_j a_s[b,h,j] (softmax stability upper bound) ----------------
__global__ __launch_bounds__(256) void asmax_kernel()
{
    int bh = blockIdx.x;
    __shared__ float sm[256];
    float m = -1e30f;
    for (int j = threadIdx.x; j < NNODE; j += 256) m = fmaxf(m, g_as[bh * NNODE + j]);
    sm[threadIdx.x] = m;
    __syncthreads();
    for (int o = 128; o; o >>= 1) {
        if (threadIdx.x < o) sm[threadIdx.x] = fmaxf(sm[threadIdx.x], sm[threadIdx.x + o]);
        __syncthreads();
    }
    if (threadIdx.x == 0) g_asmax[bh] = sm[0];
}

// ---------------- fused GAT attention: softmax(masked lrelu scores) @ V + bias + relu ----
// Block: (b, head, 64-row i tile). 256 threads = 8 warps, each warp owns 8 rows.
__global__ __launch_bounds__(256) void gat_attn_kernel(
    const float* __restrict__ wh, const float* __restrict__ gbias,
    float* __restrict__ hout)
{
    int it = blockIdx.x, hh = blockIdx.y, b = blockIdx.z;
    int i0 = it * 64;
    __shared__ float v_sm[64][64];      // V chunk [j][c]
    __shared__ float p_sm[64][64];      // P chunk transposed [j][row]
    __shared__ float as_sm[64];
    __shared__ float2 pj_sm[64];
    __shared__ float ad_sm[64], m_sm[64];
    __shared__ float2 pi_sm[64];
    __shared__ float z_sm[256];
    int tid = threadIdx.x;
    int lane = tid & 31, w = tid >> 5;
    int bh = b * HEADS + hh;

    if (tid < 64) {
        int gi = i0 + tid;
        float ad = g_ad[bh * NNODE + gi];
        ad_sm[tid] = ad;
        float mm = g_asmax[bh] + ad;             // lrelu(max a_s + a_d) >= all row scores
        m_sm[tid] = mm > 0.f ? mm : 0.2f * mm;
        pi_sm[tid] = ((const float2*)g_pos)[b * NNODE + gi];
    }
    float2 acc[8];
#pragma unroll
    for (int r = 0; r < 8; r++) acc[r] = make_float2(0.f, 0.f);
    float zacc = 0.f;
    int myrow = tid & 63, jb = tid >> 6;

    for (int ch = 0; ch < 16; ch++) {
        int j0 = ch * 64;
        const float* vg = wh + ((long long)(b * NNODE + j0)) * DIM + hh * 64;
#pragma unroll
        for (int q = 0; q < 4; q++) {
            int idx = q * 256 + tid;
            int jr = idx >> 4, sg = (idx & 15) << 2;
            *(float4*)&v_sm[jr][sg] = *(const float4*)(vg + jr * DIM + sg);
        }
        if (tid < 64) {
            as_sm[tid] = g_as[bh * NNODE + j0 + tid];
            pj_sm[tid] = ((const float2*)g_pos)[b * NNODE + j0 + tid];
        }
        __syncthreads();
        // ---- P phase: scores -> exp, data-parallel over (row, j) ----
        {
            float adr = ad_sm[myrow], mr = m_sm[myrow];
            float2 pir = pi_sm[myrow];
#pragma unroll
            for (int q = 0; q < 16; q++) {
                int jj = jb + (q << 2);
                float s = as_sm[jj] + adr;
                s = s > 0.f ? s : 0.2f * s;          // leaky relu
                float2 pj = pj_sm[jj];
                float dx = pj.x - pir.x, dy = pj.y - pir.y;
                float p;
                if (dx * dx + dy * dy < 2500.f || (j0 + jj) == (i0 + myrow))
                    p = __expf(s - mr);
                else
                    p = 0.f;
                p_sm[jj][myrow] = p;
                zacc += p;
            }
        }
        __syncthreads();
        // ---- FMA phase: acc += P^T rows * V ----
        {
            int r0 = w * 8;
#pragma unroll 4
            for (int j = 0; j < 64; j++) {
                float2 v = *(const float2*)&v_sm[j][lane * 2];
                float4 pa = *(const float4*)&p_sm[j][r0];
                float4 pb = *(const float4*)&p_sm[j][r0 + 4];
                acc[0].x = fmaf(pa.x, v.x, acc[0].x); acc[0].y = fmaf(pa.x, v.y, acc[0].y);
                acc[1].x = fmaf(pa.y, v.x, acc[1].x); acc[1].y = fmaf(pa.y, v.y, acc[1].y);
                acc[2].x = fmaf(pa.z, v.x, acc[2].x); acc[2].y = fmaf(pa.z, v.y, acc[2].y);
                acc[3].x = fmaf(pa.w, v.x, acc[3].x); acc[3].y = fmaf(pa.w, v.y, acc[3].y);
                acc[4].x = fmaf(pb.x, v.x, acc[4].x); acc[4].y = fmaf(pb.x, v.y, acc[4].y);
                acc[5].x = fmaf(pb.y, v.x, acc[5].x); acc[5].y = fmaf(pb.y, v.y, acc[5].y);
                acc[6].x = fmaf(pb.z, v.x, acc[6].x); acc[6].y = fmaf(pb.z, v.y, acc[6].y);
                acc[7].x = fmaf(pb.w, v.x, acc[7].x); acc[7].y = fmaf(pb.w, v.y, acc[7].y);
            }
        }
        __syncthreads();
    }
    // ---- normalize, bias, relu, write ----
    z_sm[tid] = zacc;
    __syncthreads();
    if (tid < 64) {
        float Z = z_sm[tid] + z_sm[tid + 64] + z_sm[tid + 128] + z_sm[tid + 192];
        z_sm[tid] = 1.f / Z;
    }
    __syncthreads();
    float2 bv = *(const float2*)(gbias + hh * 64 + lane * 2);
    int r0 = w * 8;
#pragma unroll
    for (int r = 0; r < 8; r++) {
        float rz = z_sm[r0 + r];
        float2 o;
        o.x = fmaxf(fmaf(acc[r].x, rz, bv.x), 0.f);
        o.y = fmaxf(fmaf(acc[r].y, rz, bv.y), 0.f);
        *(float2*)&hout[((long long)(b * NNODE + i0 + r0 + r)) * DIM + hh * 64 + lane * 2] = o;
    }
}

// ---------------- zero tail of output (mask = all false) ----------------
__global__ void zero_tail_kernel(float* out, long long start, long long total)
{
    long long i = start + (long long)blockIdx.x * blockDim.x + threadIdx.x;
    if (i < total) out[i] = 0.f;
}

// ---------------- launch ----------------
extern "C" void kernel_launch(void* const* d_in, const int* in_sizes, int n_in,
                              void* d_out, int out_size)
{
    const float* ego      = (const float*)d_in[0];
    const float* nbr      = (const float*)d_in[1];
    const float* node_w   = (const float*)d_in[2];
    const float* node_b   = (const float*)d_in[3];
    const float* node_g   = (const float*)d_in[4];
    const float* node_bb  = (const float*)d_in[5];
    const float* ego_w    = (const float*)d_in[6];
    const float* ego_b    = (const float*)d_in[7];
    const float* ego_g    = (const float*)d_in[8];
    const float* ego_bb   = (const float*)d_in[9];
    const float* gat_w    = (const float*)d_in[10];
    const float* gat_asrc = (const float*)d_in[11];
    const float* gat_adst = (const float*)d_in[12];
    const float* gat_b    = (const float*)d_in[13];
    const float* proj_w   = (const float*)d_in[14];
    const float* proj_b   = (const float*)d_in[15];
    float* out = (float*)d_out;

    float *h0, *h1, *wh;
    cudaGetSymbolAddress((void**)&h0, g_h0);
    cudaGetSymbolAddress((void**)&h1, g_h1);
    cudaGetSymbolAddress((void**)&wh, g_wh);

    embed_kernel<<<BATCH * NNODE, 256>>>(ego, nbr, node_w, node_b, node_g, node_bb,
                                         ego_w, ego_b, ego_g, ego_bb);

    long long hsz = (long long)BATCH * NNODE * DIM;
    if ((long long)out_size > hsz) {
        long long tail = (long long)out_size - hsz;
        int blocks = (int)((tail + 255) / 256);
        zero_tail_kernel<<<blocks, 256>>>(out, hsz, (long long)out_size);
    }

    dim3 ggrid(BATCH * NNODE / 128, 2);
    float* hbuf[2] = { h0, h1 };
    for (int l = 0; l < 2; l++) {
        sgemm256<false><<<ggrid, 256>>>(hbuf[l], gat_w + (long long)l * DIM * DIM, nullptr, wh);
        sad_kernel<<<BATCH * NNODE / 8, 256>>>(wh, gat_asrc + l * HEADS * HC,
                                               gat_adst + l * HEADS * HC);
        asmax_kernel<<<BATCH * HEADS, 256>>>();
        gat_attn_kernel<<<dim3(16, HEADS, BATCH), 256>>>(wh, gat_b + l * DIM, hbuf[1 - l]);
    }
    sgemm256<true><<<ggrid, 256>>>(h0, proj_w, proj_b, out);
}

// round 3
// speedup vs baseline: 1.5210x; 1.5210x over previous
#include <cuda_runtime.h>
#include <cstdint>

#define BATCH 16
#define NNODE 1024
#define DIM 256
#define HEADS 4
#define NBR 1023
#define TSTEPS 20

// ---------------- scratch (device globals; no allocation allowed) ----------------
__device__ float g_h0[BATCH * NNODE * DIM];
__device__ float g_h1[BATCH * NNODE * DIM];
__device__ float g_wh[BATCH * NNODE * DIM];
__device__ float g_pos[BATCH * NNODE * 2];
__device__ float g_as[BATCH * HEADS * NNODE];
__device__ float g_ad[BATCH * HEADS * NNODE];
__device__ float g_asmax[BATCH * HEADS];

// ---------------- embed: feature extract + (5->256) matmul + relu + LN ----------------
__global__ __launch_bounds__(256) void embed_kernel(
    const float* __restrict__ ego, const float* __restrict__ nbr,
    const float* __restrict__ node_w, const float* __restrict__ node_b,
    const float* __restrict__ node_g, const float* __restrict__ node_bb,
    const float* __restrict__ ego_w, const float* __restrict__ ego_b,
    const float* __restrict__ ego_g, const float* __restrict__ ego_bb)
{
    int bn = blockIdx.x;
    int b = bn >> 10, n = bn & 1023;
    int t = threadIdx.x;
    __shared__ float f[5];
    __shared__ float ws[8], wq[8];
    if (t < 5) {
        float v = (n == 0) ? ego[(b * TSTEPS + TSTEPS - 1) * 7 + t]
                           : nbr[((b * NBR + (n - 1)) * TSTEPS + TSTEPS - 1) * 11 + t];
        f[t] = v;
        if (t < 2) g_pos[bn * 2 + t] = v;
    }
    __syncthreads();
    const float *W, *bi, *g, *bb;
    if (n == 0) { W = ego_w;  bi = ego_b;  g = ego_g;  bb = ego_bb; }
    else        { W = node_w; bi = node_b; g = node_g; bb = node_bb; }
    float v = bi[t];
#pragma unroll
    for (int k = 0; k < 5; k++) v = fmaf(f[k], W[k * DIM + t], v);
    v = fmaxf(v, 0.f);
    float s = v, q = v * v;
#pragma unroll
    for (int o = 16; o; o >>= 1) {
        s += __shfl_down_sync(0xffffffffu, s, o);
        q += __shfl_down_sync(0xffffffffu, q, o);
    }
    int lane = t & 31, w = t >> 5;
    if (lane == 0) { ws[w] = s; wq[w] = q; }
    __syncthreads();
    float sum = 0.f, sq = 0.f;
#pragma unroll
    for (int i = 0; i < 8; i++) { sum += ws[i]; sq += wq[i]; }
    float mean = sum * (1.f / 256.f);
    float var = fmaxf(sq * (1.f / 256.f) - mean * mean, 0.f);
    float inv = rsqrtf(var + 1e-5f);
    g_h0[bn * DIM + t] = (v - mean) * inv * g[t] + bb[t];
}

// ---------------- SGEMM: C[M,256] = A[M,256] @ W[256,256] (+bias) ----------------
template <bool BIAS>
__global__ __launch_bounds__(256) void sgemm256(
    const float* __restrict__ A, const float* __restrict__ W,
    const float* __restrict__ bias, float* __restrict__ C)
{
    __shared__ float As[8][128];
    __shared__ float Bs[8][128];
    int tid = threadIdx.x;
    int m0 = blockIdx.x * 128, n0 = blockIdx.y * 128;
    int tx = tid & 15, ty = tid >> 4;
    int arow = tid >> 1, ac = (tid & 1) * 4;
    int brow = tid >> 5, bc = (tid & 31) * 4;
    const float* Ag = A + (m0 + arow) * 256 + ac;
    const float* Wg = W + brow * 256 + n0 + bc;
    float acc[8][8] = {};
    float4 a4 = *(const float4*)Ag;
    float4 b4 = *(const float4*)Wg;
    for (int kt = 0; kt < 32; kt++) {
        As[ac + 0][arow] = a4.x; As[ac + 1][arow] = a4.y;
        As[ac + 2][arow] = a4.z; As[ac + 3][arow] = a4.w;
        *(float4*)&Bs[brow][bc] = b4;
        __syncthreads();
        if (kt < 31) {
            a4 = *(const float4*)(Ag + (kt + 1) * 8);
            b4 = *(const float4*)(Wg + (kt + 1) * 8 * 256);
        }
#pragma unroll
        for (int k = 0; k < 8; k++) {
            float av[8], bv[8];
            *(float4*)&av[0] = *(const float4*)&As[k][ty * 8];
            *(float4*)&av[4] = *(const float4*)&As[k][ty * 8 + 4];
            *(float4*)&bv[0] = *(const float4*)&Bs[k][tx * 8];
            *(float4*)&bv[4] = *(const float4*)&Bs[k][tx * 8 + 4];
#pragma unroll
            for (int i = 0; i < 8; i++)
#pragma unroll
                for (int j = 0; j < 8; j++)
                    acc[i][j] = fmaf(av[i], bv[j], acc[i][j]);
        }
        __syncthreads();
    }
#pragma unroll
    for (int i = 0; i < 8; i++) {
        int row = m0 + ty * 8 + i;
#pragma unroll
        for (int j = 0; j < 8; j += 4) {
            float4 o = make_float4(acc[i][j], acc[i][j + 1], acc[i][j + 2], acc[i][j + 3]);
            if (BIAS) {
                float4 bv = *(const float4*)(bias + n0 + tx * 8 + j);
                o.x += bv.x; o.y += bv.y; o.z += bv.z; o.w += bv.w;
            }
            *(float4*)&C[row * 256 + n0 + tx * 8 + j] = o;
        }
    }
}

// ---------------- a_src / a_dst per (b,n,h) ----------------
__global__ __launch_bounds__(256) void sad_kernel(
    const float* __restrict__ wh,
    const float* __restrict__ asrc, const float* __restrict__ adst)
{
    int gw = (blockIdx.x * 256 + threadIdx.x) >> 5;
    int lane = threadIdx.x & 31;
    if (gw >= BATCH * NNODE) return;
    int b = gw >> 10, n = gw & 1023;
    const float* row = wh + (long long)gw * DIM;
#pragma unroll
    for (int h = 0; h < HEADS; h++) {
        float x0 = row[h * 64 + lane], x1 = row[h * 64 + 32 + lane];
        float s = x0 * asrc[h * 64 + lane] + x1 * asrc[h * 64 + 32 + lane];
        float d = x0 * adst[h * 64 + lane] + x1 * adst[h * 64 + 32 + lane];
#pragma unroll
        for (int o = 16; o; o >>= 1) {
            s += __shfl_down_sync(0xffffffffu, s, o);
            d += __shfl_down_sync(0xffffffffu, d, o);
        }
        if (lane == 0) {
            g_as[(b * HEADS + h) * NNODE + n] = s;
            g_ad[(b * HEADS + h) * NNODE + n] = d;
        }
    }
}

__global__ __launch_bounds__(256) void asmax_kernel()
{
    int bh = blockIdx.x;
    __shared__ float sm[256];
    float m = -1e30f;
    for (int j = threadIdx.x; j < NNODE; j += 256) m = fmaxf(m, g_as[bh * NNODE + j]);
    sm[threadIdx.x] = m;
    __syncthreads();
    for (int o = 128; o; o >>= 1) {
        if (threadIdx.x < o) sm[threadIdx.x] = fmaxf(sm[threadIdx.x], sm[threadIdx.x + o]);
        __syncthreads();
    }
    if (threadIdx.x == 0) g_asmax[bh] = sm[0];
}

// ======================= tf32 mma.sync helpers =======================
__device__ __forceinline__ uint32_t tf32r(float x) {
    uint32_t r;
    asm("cvt.rna.tf32.f32 %0, %1;" : "=r"(r) : "f"(x));
    return r;
}
__device__ __forceinline__ void mma_tf32(float* c, uint32_t a0, uint32_t a1,
                                         uint32_t a2, uint32_t a3,
                                         uint32_t b0, uint32_t b1) {
    asm volatile(
        "mma.sync.aligned.m16n8k8.row.col.f32.tf32.tf32.f32 "
        "{%0,%1,%2,%3}, {%4,%5,%6,%7}, {%8,%9}, {%0,%1,%2,%3};"
        : "+f"(c[0]), "+f"(c[1]), "+f"(c[2]), "+f"(c[3])
        : "r"(a0), "r"(a1), "r"(a2), "r"(a3), "r"(b0), "r"(b1));
}

// smem layout (float offsets)
#define P_STRIDE 68
#define V_STRIDE 72
#define SM_P   0
#define SM_V   8704           // 128*68
#define SM_AS  13312          // 8704 + 64*72
#define SM_PJ  13376
#define SM_AD  13504
#define SM_M   13632
#define SM_PI  13760
#define SM_Z   14016
#define ATTN_SMEM_FLOATS 14144
#define ATTN_SMEM_BYTES (ATTN_SMEM_FLOATS * 4)

// ---------------- GAT attention via tf32 mma.sync ----------------
// Block: (128-row i-tile, head, batch). Warp w owns rows w*16..w*16+15.
// D[16 x 72] per warp = P[16 x 1024] @ B, B cols 0..63 = V channels, col 64 = ones (Z).
__global__ __launch_bounds__(256) void gat_attn_mma(
    const float* __restrict__ wh, const float* __restrict__ gbias,
    float* __restrict__ hout)
{
    extern __shared__ float sm[];
    float* p_sm = sm + SM_P;
    float* v_sm = sm + SM_V;
    float* as_sm = sm + SM_AS;
    float2* pj_sm = (float2*)(sm + SM_PJ);
    float* ad_sm = sm + SM_AD;
    float* m_sm = sm + SM_M;
    float2* pi_sm = (float2*)(sm + SM_PI);
    float* z_sm = sm + SM_Z;

    int tid = threadIdx.x, w = tid >> 5, lane = tid & 31;
    int it = blockIdx.x, hh = blockIdx.y, b = blockIdx.z;
    int i0 = it * 128, bh = b * HEADS + hh;

    // per-row data
    if (tid < 128) {
        float ad = g_ad[bh * NNODE + i0 + tid];
        ad_sm[tid] = ad;
        float mm = g_asmax[bh] + ad;        // lrelu(max a_s) + a_d upper-bounds row scores
        m_sm[tid] = mm > 0.f ? mm : 0.2f * mm;
        pi_sm[tid] = ((const float2*)g_pos)[b * NNODE + i0 + tid];
    }
    // B cols 64..71: col 64 = ones (Z), 65..71 = zeros (set once; V loads only touch 0..63)
#pragma unroll
    for (int q = 0; q < 2; q++) {
        int idx = q * 256 + tid;
        int jr = idx >> 3, cc = 64 + (idx & 7);
        v_sm[jr * V_STRIDE + cc] = (cc == 64) ? 1.f : 0.f;
    }

    float acc[9][4];
#pragma unroll
    for (int n = 0; n < 9; n++)
#pragma unroll
        for (int k = 0; k < 4; k++) acc[n][k] = 0.f;

    const float* whb = wh + ((size_t)(b * NNODE)) * DIM + hh * 64;
    const float2* posb = ((const float2*)g_pos) + b * NNODE;
    int r0 = w * 16;
    int g4 = lane >> 2, q4 = lane & 3;

    for (int ch = 0; ch < 16; ch++) {
        int j0 = ch * 64;
        __syncthreads();                       // protect v_sm/as_sm reuse
        // load V chunk [64 x 64] -> v_sm (tf32-rounded)
#pragma unroll
        for (int q = 0; q < 4; q++) {
            int idx = q * 256 + tid;
            int jr = idx >> 4, cc = (idx & 15) * 4;
            float4 v = *(const float4*)(whb + (size_t)(j0 + jr) * DIM + cc);
            float* dst = v_sm + jr * V_STRIDE + cc;
            dst[0] = __uint_as_float(tf32r(v.x));
            dst[1] = __uint_as_float(tf32r(v.y));
            dst[2] = __uint_as_float(tf32r(v.z));
            dst[3] = __uint_as_float(tf32r(v.w));
        }
        if (tid < 64) {
            as_sm[tid] = g_as[bh * NNODE + j0 + tid];
            pj_sm[tid] = posb[j0 + tid];
        }
        __syncthreads();
        // ---- P phase: warp-local rows, j = lane and lane+32 ----
        {
            float as0 = as_sm[lane], as1 = as_sm[lane + 32];
            float2 pj0 = pj_sm[lane], pj1 = pj_sm[lane + 32];
            int jg0 = j0 + lane, jg1 = j0 + lane + 32;
#pragma unroll 4
            for (int r = 0; r < 16; r++) {
                int row = r0 + r;
                float adr = ad_sm[row], mr = m_sm[row];
                float2 pir = pi_sm[row];
                int ig = i0 + row;
                float s0 = as0 + adr; s0 = s0 > 0.f ? s0 : 0.2f * s0;
                float dx0 = pj0.x - pir.x, dy0 = pj0.y - pir.y;
                float e0 = __expf(s0 - mr);
                float p0 = (fmaf(dx0, dx0, dy0 * dy0) < 2500.f || jg0 == ig) ? e0 : 0.f;
                float s1 = as1 + adr; s1 = s1 > 0.f ? s1 : 0.2f * s1;
                float dx1 = pj1.x - pir.x, dy1 = pj1.y - pir.y;
                float e1 = __expf(s1 - mr);
                float p1 = (fmaf(dx1, dx1, dy1 * dy1) < 2500.f || jg1 == ig) ? e1 : 0.f;
                p_sm[row * P_STRIDE + lane] = __uint_as_float(tf32r(p0));
                p_sm[row * P_STRIDE + lane + 32] = __uint_as_float(tf32r(p1));
            }
        }
        __syncwarp();
        // ---- MMA phase: 8 k-steps of 8, 9 n-tiles of 8 ----
#pragma unroll
        for (int kb = 0; kb < 8; kb++) {
            const float* pa = p_sm + (r0 + g4) * P_STRIDE + kb * 8 + q4;
            uint32_t a0 = __float_as_uint(pa[0]);
            uint32_t a1 = __float_as_uint(pa[8 * P_STRIDE]);
            uint32_t a2 = __float_as_uint(pa[4]);
            uint32_t a3 = __float_as_uint(pa[8 * P_STRIDE + 4]);
            const float* pb = v_sm + (kb * 8 + q4) * V_STRIDE + g4;
#pragma unroll
            for (int nt = 0; nt < 9; nt++) {
                uint32_t b0 = __float_as_uint(pb[nt * 8]);
                uint32_t b1 = __float_as_uint(pb[nt * 8 + 4 * V_STRIDE]);
                mma_tf32(acc[nt], a0, a1, a2, a3, b0, b1);
            }
        }
        __syncwarp();
    }
    // ---- epilogue: Z from n-tile 8 col 0, then scale+bias+relu+store ----
    if (q4 == 0) {
        z_sm[r0 + g4] = acc[8][0];
        z_sm[r0 + g4 + 8] = acc[8][2];
    }
    __syncwarp();
    float iz0 = 1.f / z_sm[r0 + g4];
    float iz1 = 1.f / z_sm[r0 + g4 + 8];
    int rowg = i0 + r0 + g4;
    float* o0 = hout + ((size_t)(b * NNODE) + rowg) * DIM + hh * 64;
    float* o1 = o0 + 8 * DIM;
    const float* bp = gbias + hh * 64;
#pragma unroll
    for (int nt = 0; nt < 8; nt++) {
        int cc = nt * 8 + q4 * 2;
        float bx = bp[cc], by = bp[cc + 1];
        float2 u0, u1;
        u0.x = fmaxf(fmaf(acc[nt][0], iz0, bx), 0.f);
        u0.y = fmaxf(fmaf(acc[nt][1], iz0, by), 0.f);
        u1.x = fmaxf(fmaf(acc[nt][2], iz1, bx), 0.f);
        u1.y = fmaxf(fmaf(acc[nt][3], iz1, by), 0.f);
        *(float2*)(o0 + cc) = u0;
        *(float2*)(o1 + cc) = u1;
    }
}

// ---------------- zero tail of output (mask = all false) ----------------
__global__ void zero_tail_kernel(float* out, long long start, long long total)
{
    long long i = start + (long long)blockIdx.x * blockDim.x + threadIdx.x;
    if (i < total) out[i] = 0.f;
}

// ---------------- launch ----------------
extern "C" void kernel_launch(void* const* d_in, const int* in_sizes, int n_in,
                              void* d_out, int out_size)
{
    const float* ego      = (const float*)d_in[0];
    const float* nbr      = (const float*)d_in[1];
    const float* node_w   = (const float*)d_in[2];
    const float* node_b   = (const float*)d_in[3];
    const float* node_g   = (const float*)d_in[4];
    const float* node_bb  = (const float*)d_in[5];
    const float* ego_w    = (const float*)d_in[6];
    const float* ego_b    = (const float*)d_in[7];
    const float* ego_g    = (const float*)d_in[8];
    const float* ego_bb   = (const float*)d_in[9];
    const float* gat_w    = (const float*)d_in[10];
    const float* gat_asrc = (const float*)d_in[11];
    const float* gat_adst = (const float*)d_in[12];
    const float* gat_b    = (const float*)d_in[13];
    const float* proj_w   = (const float*)d_in[14];
    const float* proj_b   = (const float*)d_in[15];
    float* out = (float*)d_out;

    float *h0, *h1, *wh;
    cudaGetSymbolAddress((void**)&h0, g_h0);
    cudaGetSymbolAddress((void**)&h1, g_h1);
    cudaGetSymbolAddress((void**)&wh, g_wh);

    cudaFuncSetAttribute(gat_attn_mma, cudaFuncAttributeMaxDynamicSharedMemorySize,
                         ATTN_SMEM_BYTES);

    embed_kernel<<<BATCH * NNODE, 256>>>(ego, nbr, node_w, node_b, node_g, node_bb,
                                         ego_w, ego_b, ego_g, ego_bb);

    long long hsz = (long long)BATCH * NNODE * DIM;
    if ((long long)out_size > hsz) {
        long long tail = (long long)out_size - hsz;
        int blocks = (int)((tail + 255) / 256);
        zero_tail_kernel<<<blocks, 256>>>(out, hsz, (long long)out_size);
    }

    dim3 ggrid(BATCH * NNODE / 128, 2);
    float* hbuf[2] = { h0, h1 };
    for (int l = 0; l < 2; l++) {
        sgemm256<false><<<ggrid, 256>>>(hbuf[l], gat_w + (long long)l * DIM * DIM, nullptr, wh);
        sad_kernel<<<BATCH * NNODE / 8, 256>>>(wh, gat_asrc + l * HEADS * 64,
                                               gat_adst + l * HEADS * 64);
        asmax_kernel<<<BATCH * HEADS, 256>>>();
        gat_attn_mma<<<dim3(8, HEADS, BATCH), 256, ATTN_SMEM_BYTES>>>(
            wh, gat_b + l * DIM, hbuf[1 - l]);
    }
    sgemm256<true><<<ggrid, 256>>>(h0, proj_w, proj_b, out);
}

// round 4
// speedup vs baseline: 1.8963x; 1.2467x over previous
#include <cuda_runtime.h>
#include <cstdint>

#define BATCH 16
#define NNODE 1024
#define DIM 256
#define HEADS 4
#define NBR 1023
#define TSTEPS 20

// ---------------- scratch (device globals; no allocation allowed) ----------------
__device__ float g_h0[BATCH * NNODE * DIM];
__device__ float g_h1[BATCH * NNODE * DIM];
__device__ float g_wh[BATCH * NNODE * DIM];
__device__ float g_pos[BATCH * NNODE * 2];
__device__ float g_as[BATCH * HEADS * NNODE];
__device__ float g_ad[BATCH * HEADS * NNODE];
__device__ float g_asmax[BATCH * HEADS];

// ======================= tf32 mma.sync helpers =======================
__device__ __forceinline__ uint32_t tf32r(float x) {
    uint32_t r;
    asm("cvt.rna.tf32.f32 %0, %1;" : "=r"(r) : "f"(x));
    return r;
}
__device__ __forceinline__ void mma_tf32(float* c, uint32_t a0, uint32_t a1,
                                         uint32_t a2, uint32_t a3,
                                         uint32_t b0, uint32_t b1) {
    asm volatile(
        "mma.sync.aligned.m16n8k8.row.col.f32.tf32.tf32.f32 "
        "{%0,%1,%2,%3}, {%4,%5,%6,%7}, {%8,%9}, {%0,%1,%2,%3};"
        : "+f"(c[0]), "+f"(c[1]), "+f"(c[2]), "+f"(c[3])
        : "r"(a0), "r"(a1), "r"(a2), "r"(a3), "r"(b0), "r"(b1));
}

// ---------------- embed: feature extract + (5->256) matmul + relu + LN ----------------
__global__ __launch_bounds__(256) void embed_kernel(
    const float* __restrict__ ego, const float* __restrict__ nbr,
    const float* __restrict__ node_w, const float* __restrict__ node_b,
    const float* __restrict__ node_g, const float* __restrict__ node_bb,
    const float* __restrict__ ego_w, const float* __restrict__ ego_b,
    const float* __restrict__ ego_g, const float* __restrict__ ego_bb)
{
    int bn = blockIdx.x;
    int b = bn >> 10, n = bn & 1023;
    int t = threadIdx.x;
    __shared__ float f[5];
    __shared__ float ws[8], wq[8];
    if (t < 5) {
        float v = (n == 0) ? ego[(b * TSTEPS + TSTEPS - 1) * 7 + t]
                           : nbr[((b * NBR + (n - 1)) * TSTEPS + TSTEPS - 1) * 11 + t];
        f[t] = v;
        if (t < 2) g_pos[bn * 2 + t] = v;
    }
    __syncthreads();
    const float *W, *bi, *g, *bb;
    if (n == 0) { W = ego_w;  bi = ego_b;  g = ego_g;  bb = ego_bb; }
    else        { W = node_w; bi = node_b; g = node_g; bb = node_bb; }
    float v = bi[t];
#pragma unroll
    for (int k = 0; k < 5; k++) v = fmaf(f[k], W[k * DIM + t], v);
    v = fmaxf(v, 0.f);
    float s = v, q = v * v;
#pragma unroll
    for (int o = 16; o; o >>= 1) {
        s += __shfl_down_sync(0xffffffffu, s, o);
        q += __shfl_down_sync(0xffffffffu, q, o);
    }
    int lane = t & 31, w = t >> 5;
    if (lane == 0) { ws[w] = s; wq[w] = q; }
    __syncthreads();
    float sum = 0.f, sq = 0.f;
#pragma unroll
    for (int i = 0; i < 8; i++) { sum += ws[i]; sq += wq[i]; }
    float mean = sum * (1.f / 256.f);
    float var = fmaxf(sq * (1.f / 256.f) - mean * mean, 0.f);
    float inv = rsqrtf(var + 1e-5f);
    g_h0[bn * DIM + t] = (v - mean) * inv * g[t] + bb[t];
}

// ---------------- tf32 tensor-core GEMM: C[M,256] = A[M,256] @ W[256,256] (+bias) ----
// Block tile 128x64, 8 warps (4 M x 2 N), warp tile 32x32, K-chunk 32, reg prefetch.
#define GA_STRIDE 36
#define GB_STRIDE 72
template <bool BIAS>
__global__ __launch_bounds__(256) void tgemm256(
    const float* __restrict__ A, const float* __restrict__ W,
    const float* __restrict__ bias, float* __restrict__ C)
{
    __shared__ float As[128 * GA_STRIDE];
    __shared__ float Bs[32 * GB_STRIDE];
    int tid = threadIdx.x, w = tid >> 5, lane = tid & 31;
    int g4 = lane >> 2, q4 = lane & 3;
    int m0 = blockIdx.x * 128, n0 = blockIdx.y * 64;
    int wm = w & 3, wn = w >> 2;
    int r0 = wm * 32, c0 = wn * 32;

    // global load indices (coalesced float4)
    int af4 = tid & 7, arow = tid >> 3;          // A: 8 f4 per row, rows 0..31 (+32 strided)
    int bf4 = tid & 15, brow = tid >> 4;         // B: 16 f4 per row, rows 0..15 (+16)
    const float* Ag = A + (size_t)(m0 + arow) * 256 + af4 * 4;
    const float* Wg = W + (size_t)brow * 256 + n0 + bf4 * 4;

    float acc[2][4][4];
#pragma unroll
    for (int mt = 0; mt < 2; mt++)
#pragma unroll
        for (int nt = 0; nt < 4; nt++)
#pragma unroll
            for (int k = 0; k < 4; k++) acc[mt][nt][k] = 0.f;

    float4 pa[4], pb[2];
#pragma unroll
    for (int q = 0; q < 4; q++) pa[q] = *(const float4*)(Ag + (size_t)q * 32 * 256);
#pragma unroll
    for (int q = 0; q < 2; q++) pb[q] = *(const float4*)(Wg + (size_t)q * 16 * 256);

    for (int kc = 0; kc < 8; kc++) {
        __syncthreads();
#pragma unroll
        for (int q = 0; q < 4; q++) {
            float* d = As + (arow + q * 32) * GA_STRIDE + af4 * 4;
            d[0] = __uint_as_float(tf32r(pa[q].x));
            d[1] = __uint_as_float(tf32r(pa[q].y));
            d[2] = __uint_as_float(tf32r(pa[q].z));
            d[3] = __uint_as_float(tf32r(pa[q].w));
        }
#pragma unroll
        for (int q = 0; q < 2; q++) {
            float* d = Bs + (brow + q * 16) * GB_STRIDE + bf4 * 4;
            d[0] = __uint_as_float(tf32r(pb[q].x));
            d[1] = __uint_as_float(tf32r(pb[q].y));
            d[2] = __uint_as_float(tf32r(pb[q].z));
            d[3] = __uint_as_float(tf32r(pb[q].w));
        }
        __syncthreads();
        if (kc < 7) {
            const float* Agn = Ag + (kc + 1) * 32;
            const float* Wgn = Wg + (size_t)(kc + 1) * 32 * 256;
#pragma unroll
            for (int q = 0; q < 4; q++) pa[q] = *(const float4*)(Agn + (size_t)q * 32 * 256);
#pragma unroll
            for (int q = 0; q < 2; q++) pb[q] = *(const float4*)(Wgn + (size_t)q * 16 * 256);
        }
#pragma unroll
        for (int kb = 0; kb < 4; kb++) {
            int k8 = kb * 8;
            const float* a0p = As + (r0 + g4) * GA_STRIDE + k8 + q4;
            uint32_t a00 = __float_as_uint(a0p[0]);
            uint32_t a01 = __float_as_uint(a0p[8 * GA_STRIDE]);
            uint32_t a02 = __float_as_uint(a0p[4]);
            uint32_t a03 = __float_as_uint(a0p[8 * GA_STRIDE + 4]);
            uint32_t a10 = __float_as_uint(a0p[16 * GA_STRIDE]);
            uint32_t a11 = __float_as_uint(a0p[24 * GA_STRIDE]);
            uint32_t a12 = __float_as_uint(a0p[16 * GA_STRIDE + 4]);
            uint32_t a13 = __float_as_uint(a0p[24 * GA_STRIDE + 4]);
            const float* bp = Bs + (k8 + q4) * GB_STRIDE + c0 + g4;
#pragma unroll
            for (int nt = 0; nt < 4; nt++) {
                uint32_t b0 = __float_as_uint(bp[nt * 8]);
                uint32_t b1 = __float_as_uint(bp[nt * 8 + 4 * GB_STRIDE]);
                mma_tf32(acc[0][nt], a00, a01, a02, a03, b0, b1);
                mma_tf32(acc[1][nt], a10, a11, a12, a13, b0, b1);
            }
        }
    }
    // epilogue
#pragma unroll
    for (int mt = 0; mt < 2; mt++) {
        int row = m0 + r0 + mt * 16 + g4;
        float* c0p = C + (size_t)row * 256 + n0 + c0;
        float* c1p = c0p + 8 * 256;
#pragma unroll
        for (int nt = 0; nt < 4; nt++) {
            int cc = nt * 8 + q4 * 2;
            float bx = 0.f, by = 0.f;
            if (BIAS) { bx = bias[n0 + c0 + cc]; by = bias[n0 + c0 + cc + 1]; }
            float2 u0, u1;
            u0.x = acc[mt][nt][0] + bx; u0.y = acc[mt][nt][1] + by;
            u1.x = acc[mt][nt][2] + bx; u1.y = acc[mt][nt][3] + by;
            *(float2*)(c0p + cc) = u0;
            *(float2*)(c1p + cc) = u1;
        }
    }
}

// ---------------- a_src / a_dst per (b,n,h) ----------------
__global__ __launch_bounds__(256) void sad_kernel(
    const float* __restrict__ wh,
    const float* __restrict__ asrc, const float* __restrict__ adst)
{
    int gw = (blockIdx.x * 256 + threadIdx.x) >> 5;
    int lane = threadIdx.x & 31;
    if (gw >= BATCH * NNODE) return;
    int b = gw >> 10, n = gw & 1023;
    const float* row = wh + (long long)gw * DIM;
#pragma unroll
    for (int h = 0; h < HEADS; h++) {
        float x0 = row[h * 64 + lane], x1 = row[h * 64 + 32 + lane];
        float s = x0 * asrc[h * 64 + lane] + x1 * asrc[h * 64 + 32 + lane];
        float d = x0 * adst[h * 64 + lane] + x1 * adst[h * 64 + 32 + lane];
#pragma unroll
        for (int o = 16; o; o >>= 1) {
            s += __shfl_down_sync(0xffffffffu, s, o);
            d += __shfl_down_sync(0xffffffffu, d, o);
        }
        if (lane == 0) {
            g_as[(b * HEADS + h) * NNODE + n] = s;
            g_ad[(b * HEADS + h) * NNODE + n] = d;
        }
    }
}

__global__ __launch_bounds__(256) void asmax_kernel()
{
    int bh = blockIdx.x;
    __shared__ float sm[256];
    float m = -1e30f;
    for (int j = threadIdx.x; j < NNODE; j += 256) m = fmaxf(m, g_as[bh * NNODE + j]);
    sm[threadIdx.x] = m;
    __syncthreads();
    for (int o = 128; o; o >>= 1) {
        if (threadIdx.x < o) sm[threadIdx.x] = fmaxf(sm[threadIdx.x], sm[threadIdx.x + o]);
        __syncthreads();
    }
    if (threadIdx.x == 0) g_asmax[bh] = sm[0];
}

// smem layout (float offsets)
#define P_STRIDE 68
#define V_STRIDE 72
#define SM_P   0
#define SM_V   8704           // 128*68
#define SM_AS  13312          // 8704 + 64*72
#define SM_PJ  13376
#define SM_AD  13504
#define SM_M   13632
#define SM_PI  13760
#define SM_Z   14016
#define ATTN_SMEM_FLOATS 14144
#define ATTN_SMEM_BYTES (ATTN_SMEM_FLOATS * 4)

// ---------------- GAT attention via tf32 mma.sync ----------------
__global__ __launch_bounds__(256) void gat_attn_mma(
    const float* __restrict__ wh, const float* __restrict__ gbias,
    float* __restrict__ hout)
{
    extern __shared__ float sm[];
    float* p_sm = sm + SM_P;
    float* v_sm = sm + SM_V;
    float* as_sm = sm + SM_AS;
    float2* pj_sm = (float2*)(sm + SM_PJ);
    float* ad_sm = sm + SM_AD;
    float* m_sm = sm + SM_M;
    float2* pi_sm = (float2*)(sm + SM_PI);
    float* z_sm = sm + SM_Z;

    int tid = threadIdx.x, w = tid >> 5, lane = tid & 31;
    int it = blockIdx.x, hh = blockIdx.y, b = blockIdx.z;
    int i0 = it * 128, bh = b * HEADS + hh;

    if (tid < 128) {
        float ad = g_ad[bh * NNODE + i0 + tid];
        ad_sm[tid] = ad;
        float mm = g_asmax[bh] + ad;
        m_sm[tid] = mm > 0.f ? mm : 0.2f * mm;
        pi_sm[tid] = ((const float2*)g_pos)[b * NNODE + i0 + tid];
    }
#pragma unroll
    for (int q = 0; q < 2; q++) {
        int idx = q * 256 + tid;
        int jr = idx >> 3, cc = 64 + (idx & 7);
        v_sm[jr * V_STRIDE + cc] = (cc == 64) ? 1.f : 0.f;
    }

    float acc[9][4];
#pragma unroll
    for (int n = 0; n < 9; n++)
#pragma unroll
        for (int k = 0; k < 4; k++) acc[n][k] = 0.f;

    const float* whb = wh + ((size_t)(b * NNODE)) * DIM + hh * 64;
    const float2* posb = ((const float2*)g_pos) + b * NNODE;
    int r0 = w * 16;
    int g4 = lane >> 2, q4 = lane & 3;

    for (int ch = 0; ch < 16; ch++) {
        int j0 = ch * 64;
        __syncthreads();
#pragma unroll
        for (int q = 0; q < 4; q++) {
            int idx = q * 256 + tid;
            int jr = idx >> 4, cc = (idx & 15) * 4;
            float4 v = *(const float4*)(whb + (size_t)(j0 + jr) * DIM + cc);
            float* dst = v_sm + jr * V_STRIDE + cc;
            dst[0] = __uint_as_float(tf32r(v.x));
            dst[1] = __uint_as_float(tf32r(v.y));
            dst[2] = __uint_as_float(tf32r(v.z));
            dst[3] = __uint_as_float(tf32r(v.w));
        }
        if (tid < 64) {
            as_sm[tid] = g_as[bh * NNODE + j0 + tid];
            pj_sm[tid] = posb[j0 + tid];
        }
        __syncthreads();
        {
            float as0 = as_sm[lane], as1 = as_sm[lane + 32];
            float2 pj0 = pj_sm[lane], pj1 = pj_sm[lane + 32];
            int jg0 = j0 + lane, jg1 = j0 + lane + 32;
#pragma unroll 4
            for (int r = 0; r < 16; r++) {
                int row = r0 + r;
                float adr = ad_sm[row], mr = m_sm[row];
                float2 pir = pi_sm[row];
                int ig = i0 + row;
                float s0 = as0 + adr; s0 = s0 > 0.f ? s0 : 0.2f * s0;
                float dx0 = pj0.x - pir.x, dy0 = pj0.y - pir.y;
                float e0 = __expf(s0 - mr);
                float p0 = (fmaf(dx0, dx0, dy0 * dy0) < 2500.f || jg0 == ig) ? e0 : 0.f;
                float s1 = as1 + adr; s1 = s1 > 0.f ? s1 : 0.2f * s1;
                float dx1 = pj1.x - pir.x, dy1 = pj1.y - pir.y;
                float e1 = __expf(s1 - mr);
                float p1 = (fmaf(dx1, dx1, dy1 * dy1) < 2500.f || jg1 == ig) ? e1 : 0.f;
                p_sm[row * P_STRIDE + lane] = __uint_as_float(tf32r(p0));
                p_sm[row * P_STRIDE + lane + 32] = __uint_as_float(tf32r(p1));
            }
        }
        __syncwarp();
#pragma unroll
        for (int kb = 0; kb < 8; kb++) {
            const float* pa = p_sm + (r0 + g4) * P_STRIDE + kb * 8 + q4;
            uint32_t a0 = __float_as_uint(pa[0]);
            uint32_t a1 = __float_as_uint(pa[8 * P_STRIDE]);
            uint32_t a2 = __float_as_uint(pa[4]);
            uint32_t a3 = __float_as_uint(pa[8 * P_STRIDE + 4]);
            const float* pb = v_sm + (kb * 8 + q4) * V_STRIDE + g4;
#pragma unroll
            for (int nt = 0; nt < 9; nt++) {
                uint32_t b0 = __float_as_uint(pb[nt * 8]);
                uint32_t b1 = __float_as_uint(pb[nt * 8 + 4 * V_STRIDE]);
                mma_tf32(acc[nt], a0, a1, a2, a3, b0, b1);
            }
        }
        __syncwarp();
    }
    if (q4 == 0) {
        z_sm[r0 + g4] = acc[8][0];
        z_sm[r0 + g4 + 8] = acc[8][2];
    }
    __syncwarp();
    float iz0 = 1.f / z_sm[r0 + g4];
    float iz1 = 1.f / z_sm[r0 + g4 + 8];
    int rowg = i0 + r0 + g4;
    float* o0 = hout + ((size_t)(b * NNODE) + rowg) * DIM + hh * 64;
    float* o1 = o0 + 8 * DIM;
    const float* bp = gbias + hh * 64;
#pragma unroll
    for (int nt = 0; nt < 8; nt++) {
        int cc = nt * 8 + q4 * 2;
        float bx = bp[cc], by = bp[cc + 1];
        float2 u0, u1;
        u0.x = fmaxf(fmaf(acc[nt][0], iz0, bx), 0.f);
        u0.y = fmaxf(fmaf(acc[nt][1], iz0, by), 0.f);
        u1.x = fmaxf(fmaf(acc[nt][2], iz1, bx), 0.f);
        u1.y = fmaxf(fmaf(acc[nt][3], iz1, by), 0.f);
        *(float2*)(o0 + cc) = u0;
        *(float2*)(o1 + cc) = u1;
    }
}

// ---------------- zero tail of output (mask = all false) ----------------
__global__ void zero_tail_kernel(float* out, long long start, long long total)
{
    long long i = start + (long long)blockIdx.x * blockDim.x + threadIdx.x;
    if (i < total) out[i] = 0.f;
}

// ---------------- launch ----------------
extern "C" void kernel_launch(void* const* d_in, const int* in_sizes, int n_in,
                              void* d_out, int out_size)
{
    const float* ego      = (const float*)d_in[0];
    const float* nbr      = (const float*)d_in[1];
    const float* node_w   = (const float*)d_in[2];
    const float* node_b   = (const float*)d_in[3];
    const float* node_g   = (const float*)d_in[4];
    const float* node_bb  = (const float*)d_in[5];
    const float* ego_w    = (const float*)d_in[6];
    const float* ego_b    = (const float*)d_in[7];
    const float* ego_g    = (const float*)d_in[8];
    const float* ego_bb   = (const float*)d_in[9];
    const float* gat_w    = (const float*)d_in[10];
    const float* gat_asrc = (const float*)d_in[11];
    const float* gat_adst = (const float*)d_in[12];
    const float* gat_b    = (const float*)d_in[13];
    const float* proj_w   = (const float*)d_in[14];
    const float* proj_b   = (const float*)d_in[15];
    float* out = (float*)d_out;

    float *h0, *h1, *wh;
    cudaGetSymbolAddress((void**)&h0, g_h0);
    cudaGetSymbolAddress((void**)&h1, g_h1);
    cudaGetSymbolAddress((void**)&wh, g_wh);

    cudaFuncSetAttribute(gat_attn_mma, cudaFuncAttributeMaxDynamicSharedMemorySize,
                         ATTN_SMEM_BYTES);

    embed_kernel<<<BATCH * NNODE, 256>>>(ego, nbr, node_w, node_b, node_g, node_bb,
                                         ego_w, ego_b, ego_g, ego_bb);

    long long hsz = (long long)BATCH * NNODE * DIM;
    if ((long long)out_size > hsz) {
        long long tail = (long long)out_size - hsz;
        int blocks = (int)((tail + 255) / 256);
        zero_tail_kernel<<<blocks, 256>>>(out, hsz, (long long)out_size);
    }

    dim3 ggrid(BATCH * NNODE / 128, 4);
    float* hbuf[2] = { h0, h1 };
    for (int l = 0; l < 2; l++) {
        tgemm256<false><<<ggrid, 256>>>(hbuf[l], gat_w + (long long)l * DIM * DIM, nullptr, wh);
        sad_kernel<<<BATCH * NNODE / 8, 256>>>(wh, gat_asrc + l * HEADS * 64,
                                               gat_adst + l * HEADS * 64);
        asmax_kernel<<<BATCH * HEADS, 256>>>();
        gat_attn_mma<<<dim3(8, HEADS, BATCH), 256, ATTN_SMEM_BYTES>>>(
            wh, gat_b + l * DIM, hbuf[1 - l]);
    }
    tgemm256<true><<<ggrid, 256>>>(h0, proj_w, proj_b, out);
}

// round 5
// speedup vs baseline: 2.1856x; 1.1526x over previous
#include <cuda_runtime.h>
#include <cstdint>

#define BATCH 16
#define NNODE 1024
#define DIM 256
#define HEADS 4
#define NBR 1023
#define TSTEPS 20

// ---------------- scratch (device globals; no allocation allowed) ----------------
__device__ float g_h0[BATCH * NNODE * DIM];
__device__ float g_h1[BATCH * NNODE * DIM];
__device__ float g_wh[BATCH * NNODE * DIM];
__device__ float g_pos[BATCH * NNODE * 2];
__device__ float g_as[BATCH * HEADS * NNODE];
__device__ float g_ad[BATCH * HEADS * NNODE];
__device__ float g_asmax[BATCH * HEADS];
__device__ uint32_t g_adjT[BATCH * 32 * NNODE];   // [b][jword][i] bit lane = j%32

// ======================= tf32 mma.sync helpers =======================
__device__ __forceinline__ uint32_t tf32r(float x) {
    uint32_t r;
    asm("cvt.rna.tf32.f32 %0, %1;" : "=r"(r) : "f"(x));
    return r;
}
__device__ __forceinline__ void mma_tf32(float* c, uint32_t a0, uint32_t a1,
                                         uint32_t a2, uint32_t a3,
                                         uint32_t b0, uint32_t b1) {
    asm volatile(
        "mma.sync.aligned.m16n8k8.row.col.f32.tf32.tf32.f32 "
        "{%0,%1,%2,%3}, {%4,%5,%6,%7}, {%8,%9}, {%0,%1,%2,%3};"
        : "+f"(c[0]), "+f"(c[1]), "+f"(c[2]), "+f"(c[3])
        : "r"(a0), "r"(a1), "r"(a2), "r"(a3), "r"(b0), "r"(b1));
}

// ---------------- embed: 8 nodes per block, weight col in regs ----------------
__global__ __launch_bounds__(256) void embed_kernel(
    const float* __restrict__ ego, const float* __restrict__ nbr,
    const float* __restrict__ node_w, const float* __restrict__ node_b,
    const float* __restrict__ node_g, const float* __restrict__ node_bb,
    const float* __restrict__ ego_w, const float* __restrict__ ego_b,
    const float* __restrict__ ego_g, const float* __restrict__ ego_bb)
{
    int t = threadIdx.x;
    int bn0 = blockIdx.x * 8;
    __shared__ float f[8][5];
    __shared__ float ws[8][8], wq[8][8];
    if (t < 40) {
        int nn = t / 5, k = t - nn * 5;
        int bn = bn0 + nn;
        int b = bn >> 10, n = bn & 1023;
        float v = (n == 0) ? ego[(b * TSTEPS + TSTEPS - 1) * 7 + k]
                           : nbr[((b * NBR + (n - 1)) * TSTEPS + TSTEPS - 1) * 11 + k];
        f[nn][k] = v;
        if (k < 2) g_pos[bn * 2 + k] = v;
    }
    __syncthreads();
    float wn[5];
#pragma unroll
    for (int k = 0; k < 5; k++) wn[k] = node_w[k * DIM + t];
    float nb = node_b[t];
    int lane = t & 31, w = t >> 5;
    float vv[8];
#pragma unroll
    for (int nn = 0; nn < 8; nn++) {
        int n = (bn0 + nn) & 1023;
        float v;
        if (n == 0) {
            v = ego_b[t];
#pragma unroll
            for (int k = 0; k < 5; k++) v = fmaf(f[nn][k], ego_w[k * DIM + t], v);
        } else {
            v = nb;
#pragma unroll
            for (int k = 0; k < 5; k++) v = fmaf(f[nn][k], wn[k], v);
        }
        v = fmaxf(v, 0.f);
        vv[nn] = v;
        float s = v, q = v * v;
#pragma unroll
        for (int o = 16; o; o >>= 1) {
            s += __shfl_down_sync(0xffffffffu, s, o);
            q += __shfl_down_sync(0xffffffffu, q, o);
        }
        if (lane == 0) { ws[nn][w] = s; wq[nn][w] = q; }
    }
    __syncthreads();
    float ng = node_g[t], nbb = node_bb[t];
#pragma unroll
    for (int nn = 0; nn < 8; nn++) {
        int bn = bn0 + nn;
        int n = bn & 1023;
        float sum = 0.f, sq = 0.f;
#pragma unroll
        for (int i = 0; i < 8; i++) { sum += ws[nn][i]; sq += wq[nn][i]; }
        float mean = sum * (1.f / 256.f);
        float var = fmaxf(sq * (1.f / 256.f) - mean * mean, 0.f);
        float inv = rsqrtf(var + 1e-5f);
        float gg = ng, bb2 = nbb;
        if (n == 0) { gg = ego_g[t]; bb2 = ego_bb[t]; }
        g_h0[(size_t)bn * DIM + t] = (vv[nn] - mean) * inv * gg + bb2;
    }
}

// ---------------- adjacency bitmask: g_adjT[b][jw][i], bit l = adj(i, jw*32+l) ----
__global__ __launch_bounds__(256) void adj_kernel()
{
    int b = blockIdx.z, jw = blockIdx.y;
    int lane = threadIdx.x & 31, w = threadIdx.x >> 5;
    int j = jw * 32 + lane;
    float2 pj = ((const float2*)g_pos)[b * NNODE + j];
    int i0 = blockIdx.x * 32 + w;
#pragma unroll
    for (int q = 0; q < 4; q++) {
        int i = i0 + q * 8;
        float2 pi = ((const float2*)g_pos)[b * NNODE + i];
        float dx = pj.x - pi.x, dy = pj.y - pi.y;
        bool a = (fmaf(dx, dx, dy * dy) < 2500.f) || (i == j);
        uint32_t word = __ballot_sync(0xffffffffu, a);
        if (lane == 0) g_adjT[(b * 32 + jw) * NNODE + i] = word;
    }
}

// ---------------- tf32 tensor-core GEMM: C[M,256] = A[M,256] @ W[256,256] (+bias) ----
#define GA_STRIDE 36
#define GB_STRIDE 72
template <bool BIAS>
__global__ __launch_bounds__(256) void tgemm256(
    const float* __restrict__ A, const float* __restrict__ W,
    const float* __restrict__ bias, float* __restrict__ C)
{
    __shared__ float As[128 * GA_STRIDE];
    __shared__ float Bs[32 * GB_STRIDE];
    int tid = threadIdx.x, w = tid >> 5, lane = tid & 31;
    int g4 = lane >> 2, q4 = lane & 3;
    int m0 = blockIdx.x * 128, n0 = blockIdx.y * 64;
    int wm = w & 3, wn = w >> 2;
    int r0 = wm * 32, c0 = wn * 32;

    int af4 = tid & 7, arow = tid >> 3;
    int bf4 = tid & 15, brow = tid >> 4;
    const float* Ag = A + (size_t)(m0 + arow) * 256 + af4 * 4;
    const float* Wg = W + (size_t)brow * 256 + n0 + bf4 * 4;

    float acc[2][4][4];
#pragma unroll
    for (int mt = 0; mt < 2; mt++)
#pragma unroll
        for (int nt = 0; nt < 4; nt++)
#pragma unroll
            for (int k = 0; k < 4; k++) acc[mt][nt][k] = 0.f;

    float4 pa[4], pb[2];
#pragma unroll
    for (int q = 0; q < 4; q++) pa[q] = *(const float4*)(Ag + (size_t)q * 32 * 256);
#pragma unroll
    for (int q = 0; q < 2; q++) pb[q] = *(const float4*)(Wg + (size_t)q * 16 * 256);

    for (int kc = 0; kc < 8; kc++) {
        __syncthreads();
#pragma unroll
        for (int q = 0; q < 4; q++) {
            float* d = As + (arow + q * 32) * GA_STRIDE + af4 * 4;
            d[0] = __uint_as_float(tf32r(pa[q].x));
            d[1] = __uint_as_float(tf32r(pa[q].y));
            d[2] = __uint_as_float(tf32r(pa[q].z));
            d[3] = __uint_as_float(tf32r(pa[q].w));
        }
#pragma unroll
        for (int q = 0; q < 2; q++) {
            float* d = Bs + (brow + q * 16) * GB_STRIDE + bf4 * 4;
            d[0] = __uint_as_float(tf32r(pb[q].x));
            d[1] = __uint_as_float(tf32r(pb[q].y));
            d[2] = __uint_as_float(tf32r(pb[q].z));
            d[3] = __uint_as_float(tf32r(pb[q].w));
        }
        __syncthreads();
        if (kc < 7) {
            const float* Agn = Ag + (kc + 1) * 32;
            const float* Wgn = Wg + (size_t)(kc + 1) * 32 * 256;
#pragma unroll
            for (int q = 0; q < 4; q++) pa[q] = *(const float4*)(Agn + (size_t)q * 32 * 256);
#pragma unroll
            for (int q = 0; q < 2; q++) pb[q] = *(const float4*)(Wgn + (size_t)q * 16 * 256);
        }
#pragma unroll
        for (int kb = 0; kb < 4; kb++) {
            int k8 = kb * 8;
            const float* a0p = As + (r0 + g4) * GA_STRIDE + k8 + q4;
            uint32_t a00 = __float_as_uint(a0p[0]);
            uint32_t a01 = __float_as_uint(a0p[8 * GA_STRIDE]);
            uint32_t a02 = __float_as_uint(a0p[4]);
            uint32_t a03 = __float_as_uint(a0p[8 * GA_STRIDE + 4]);
            uint32_t a10 = __float_as_uint(a0p[16 * GA_STRIDE]);
            uint32_t a11 = __float_as_uint(a0p[24 * GA_STRIDE]);
            uint32_t a12 = __float_as_uint(a0p[16 * GA_STRIDE + 4]);
            uint32_t a13 = __float_as_uint(a0p[24 * GA_STRIDE + 4]);
            const float* bp = Bs + (k8 + q4) * GB_STRIDE + c0 + g4;
#pragma unroll
            for (int nt = 0; nt < 4; nt++) {
                uint32_t b0 = __float_as_uint(bp[nt * 8]);
                uint32_t b1 = __float_as_uint(bp[nt * 8 + 4 * GB_STRIDE]);
                mma_tf32(acc[0][nt], a00, a01, a02, a03, b0, b1);
                mma_tf32(acc[1][nt], a10, a11, a12, a13, b0, b1);
            }
        }
    }
#pragma unroll
    for (int mt = 0; mt < 2; mt++) {
        int row = m0 + r0 + mt * 16 + g4;
        float* c0p = C + (size_t)row * 256 + n0 + c0;
        float* c1p = c0p + 8 * 256;
#pragma unroll
        for (int nt = 0; nt < 4; nt++) {
            int cc = nt * 8 + q4 * 2;
            float bx = 0.f, by = 0.f;
            if (BIAS) { bx = bias[n0 + c0 + cc]; by = bias[n0 + c0 + cc + 1]; }
            float2 u0, u1;
            u0.x = acc[mt][nt][0] + bx; u0.y = acc[mt][nt][1] + by;
            u1.x = acc[mt][nt][2] + bx; u1.y = acc[mt][nt][3] + by;
            *(float2*)(c0p + cc) = u0;
            *(float2*)(c1p + cc) = u1;
        }
    }
}

// ---------------- a_src / a_dst per (b,n,h) ----------------
__global__ __launch_bounds__(256) void sad_kernel(
    const float* __restrict__ wh,
    const float* __restrict__ asrc, const float* __restrict__ adst)
{
    int gw = (blockIdx.x * 256 + threadIdx.x) >> 5;
    int lane = threadIdx.x & 31;
    if (gw >= BATCH * NNODE) return;
    int b = gw >> 10, n = gw & 1023;
    const float* row = wh + (long long)gw * DIM;
#pragma unroll
    for (int h = 0; h < HEADS; h++) {
        float x0 = row[h * 64 + lane], x1 = row[h * 64 + 32 + lane];
        float s = x0 * asrc[h * 64 + lane] + x1 * asrc[h * 64 + 32 + lane];
        float d = x0 * adst[h * 64 + lane] + x1 * adst[h * 64 + 32 + lane];
#pragma unroll
        for (int o = 16; o; o >>= 1) {
            s += __shfl_down_sync(0xffffffffu, s, o);
            d += __shfl_down_sync(0xffffffffu, d, o);
        }
        if (lane == 0) {
            g_as[(b * HEADS + h) * NNODE + n] = s;
            g_ad[(b * HEADS + h) * NNODE + n] = d;
        }
    }
}

__global__ __launch_bounds__(256) void asmax_kernel()
{
    int bh = blockIdx.x;
    __shared__ float sm[256];
    float m = -1e30f;
    for (int j = threadIdx.x; j < NNODE; j += 256) m = fmaxf(m, g_as[bh * NNODE + j]);
    sm[threadIdx.x] = m;
    __syncthreads();
    for (int o = 128; o; o >>= 1) {
        if (threadIdx.x < o) sm[threadIdx.x] = fmaxf(sm[threadIdx.x], sm[threadIdx.x + o]);
        __syncthreads();
    }
    if (threadIdx.x == 0) g_asmax[bh] = sm[0];
}

// smem layout (float offsets) for attention
#define P_STRIDE 68
#define V_STRIDE 72
#define SM_P   0
#define SM_V   8704            // 128*68
#define SM_AS  13312           // 8704 + 64*72
#define SM_AD  13376
#define SM_M   13504
#define SM_ADJ 13632           // 256 u32
#define ATTN_SMEM_FLOATS 13888
#define ATTN_SMEM_BYTES (ATTN_SMEM_FLOATS * 4)

// ---------------- GAT attention: 128 threads, 4 warps x 32 rows, tf32 mma.sync ----
// D[128 x 72] = P[128 x 1024] @ B; B cols 0..63 = V channels, col 64 = ones (Z).
__global__ __launch_bounds__(128, 4) void gat_attn_mma(
    const float* __restrict__ wh, const float* __restrict__ gbias,
    float* __restrict__ hout)
{
    extern __shared__ float sm[];
    float* p_sm = sm + SM_P;
    float* v_sm = sm + SM_V;
    float* as_sm = sm + SM_AS;
    float* ad_sm = sm + SM_AD;
    float* m_sm = sm + SM_M;
    uint32_t* adj_sm = (uint32_t*)(sm + SM_ADJ);

    int tid = threadIdx.x, w = tid >> 5, lane = tid & 31;
    int g4 = lane >> 2, q4 = lane & 3;
    int it = blockIdx.x, hh = blockIdx.y, b = blockIdx.z;
    int i0 = it * 128, bh = b * HEADS + hh;
    int r0 = w * 32;

    // per-row constants (128 rows, 128 threads)
    {
        float ad = g_ad[bh * NNODE + i0 + tid];
        ad_sm[tid] = ad;
        float mm = g_asmax[bh] + ad;
        m_sm[tid] = mm > 0.f ? mm : 0.2f * mm;
    }
    // B cols 64..71: col 64 = ones (Z), rest zeros
#pragma unroll
    for (int q = 0; q < 4; q++) {
        int idx = q * 128 + tid;
        int jr = idx >> 3, cc = 64 + (idx & 7);
        v_sm[jr * V_STRIDE + cc] = (cc == 64) ? 1.f : 0.f;
    }

    float acc[2][9][4];
#pragma unroll
    for (int mt = 0; mt < 2; mt++)
#pragma unroll
        for (int n = 0; n < 9; n++)
#pragma unroll
            for (int k = 0; k < 4; k++) acc[mt][n][k] = 0.f;

    const float* whb = wh + ((size_t)(b * NNODE)) * DIM + hh * 64;
    const uint32_t* adjb = g_adjT + (size_t)b * 32 * NNODE + i0;

    for (int ch = 0; ch < 16; ch++) {
        int j0 = ch * 64;
        __syncthreads();
        // V chunk [64 x 64] -> v_sm (tf32-rounded), 8 float4 per thread
#pragma unroll
        for (int q = 0; q < 8; q++) {
            int idx = q * 128 + tid;
            int jr = idx >> 4, cc = (idx & 15) * 4;
            float4 v = *(const float4*)(whb + (size_t)(j0 + jr) * DIM + cc);
            float* dst = v_sm + jr * V_STRIDE + cc;
            dst[0] = __uint_as_float(tf32r(v.x));
            dst[1] = __uint_as_float(tf32r(v.y));
            dst[2] = __uint_as_float(tf32r(v.z));
            dst[3] = __uint_as_float(tf32r(v.w));
        }
        if (tid < 64) as_sm[tid] = g_as[bh * NNODE + j0 + tid];
        adj_sm[tid] = adjb[(size_t)(2 * ch) * NNODE + tid];
        adj_sm[128 + tid] = adjb[(size_t)(2 * ch + 1) * NNODE + tid];
        __syncthreads();
        // ---- P phase: warp rows r0..r0+31, lane covers j=lane, lane+32 ----
        {
            float as0 = as_sm[lane], as1 = as_sm[lane + 32];
#pragma unroll 4
            for (int r = 0; r < 32; r++) {
                int row = r0 + r;
                float adr = ad_sm[row], mr = m_sm[row];
                uint32_t A0 = adj_sm[row], A1 = adj_sm[128 + row];
                float t0 = as0 + adr;
                float s0 = fmaxf(t0, 0.2f * t0);
                float e0 = __expf(s0 - mr);
                float p0 = ((A0 >> lane) & 1u) ? e0 : 0.f;
                float t1 = as1 + adr;
                float s1 = fmaxf(t1, 0.2f * t1);
                float e1 = __expf(s1 - mr);
                float p1 = ((A1 >> lane) & 1u) ? e1 : 0.f;
                p_sm[row * P_STRIDE + lane] = __uint_as_float(tf32r(p0));
                p_sm[row * P_STRIDE + lane + 32] = __uint_as_float(tf32r(p1));
            }
        }
        __syncwarp();
        // ---- MMA phase: 8 k-steps, 9 n-tiles, 2 m-tiles ----
#pragma unroll
        for (int kb = 0; kb < 8; kb++) {
            const float* pa = p_sm + (r0 + g4) * P_STRIDE + kb * 8 + q4;
            uint32_t a00 = __float_as_uint(pa[0]);
            uint32_t a01 = __float_as_uint(pa[8 * P_STRIDE]);
            uint32_t a02 = __float_as_uint(pa[4]);
            uint32_t a03 = __float_as_uint(pa[8 * P_STRIDE + 4]);
            uint32_t a10 = __float_as_uint(pa[16 * P_STRIDE]);
            uint32_t a11 = __float_as_uint(pa[24 * P_STRIDE]);
            uint32_t a12 = __float_as_uint(pa[16 * P_STRIDE + 4]);
            uint32_t a13 = __float_as_uint(pa[24 * P_STRIDE + 4]);
            const float* pb = v_sm + (kb * 8 + q4) * V_STRIDE + g4;
#pragma unroll
            for (int nt = 0; nt < 9; nt++) {
                uint32_t b0 = __float_as_uint(pb[nt * 8]);
                uint32_t b1 = __float_as_uint(pb[nt * 8 + 4 * V_STRIDE]);
                mma_tf32(acc[0][nt], a00, a01, a02, a03, b0, b1);
                mma_tf32(acc[1][nt], a10, a11, a12, a13, b0, b1);
            }
        }
        __syncwarp();
    }
    // ---- epilogue: Z from n-tile 8 (col 64, held by q4==0), bcast via shfl ----
    const float* bp = gbias + hh * 64;
#pragma unroll
    for (int mt = 0; mt < 2; mt++) {
        float z0 = __shfl_sync(0xffffffffu, acc[mt][8][0], lane & 28);
        float z1 = __shfl_sync(0xffffffffu, acc[mt][8][2], lane & 28);
        float iz0 = 1.f / z0;
        float iz1 = 1.f / z1;
        int rowg = i0 + r0 + mt * 16 + g4;
        float* o0 = hout + ((size_t)(b * NNODE) + rowg) * DIM + hh * 64;
        float* o1 = o0 + 8 * DIM;
#pragma unroll
        for (int nt = 0; nt < 8; nt++) {
            int cc = nt * 8 + q4 * 2;
            float bx = bp[cc], by = bp[cc + 1];
            float2 u0, u1;
            u0.x = fmaxf(fmaf(acc[mt][nt][0], iz0, bx), 0.f);
            u0.y = fmaxf(fmaf(acc[mt][nt][1], iz0, by), 0.f);
            u1.x = fmaxf(fmaf(acc[mt][nt][2], iz1, bx), 0.f);
            u1.y = fmaxf(fmaf(acc[mt][nt][3], iz1, by), 0.f);
            *(float2*)(o0 + cc) = u0;
            *(float2*)(o1 + cc) = u1;
        }
    }
}

// ---------------- zero tail of output (mask = all false) ----------------
__global__ void zero_tail_kernel(float* out, long long start, long long total)
{
    long long i = start + (long long)blockIdx.x * blockDim.x + threadIdx.x;
    if (i < total) out[i] = 0.f;
}

// ---------------- launch ----------------
extern "C" void kernel_launch(void* const* d_in, const int* in_sizes, int n_in,
                              void* d_out, int out_size)
{
    const float* ego      = (const float*)d_in[0];
    const float* nbr      = (const float*)d_in[1];
    const float* node_w   = (const float*)d_in[2];
    const float* node_b   = (const float*)d_in[3];
    const float* node_g   = (const float*)d_in[4];
    const float* node_bb  = (const float*)d_in[5];
    const float* ego_w    = (const float*)d_in[6];
    const float* ego_b    = (const float*)d_in[7];
    const float* ego_g    = (const float*)d_in[8];
    const float* ego_bb   = (const float*)d_in[9];
    const float* gat_w    = (const float*)d_in[10];
    const float* gat_asrc = (const float*)d_in[11];
    const float* gat_adst = (const float*)d_in[12];
    const float* gat_b    = (const float*)d_in[13];
    const float* proj_w   = (const float*)d_in[14];
    const float* proj_b   = (const float*)d_in[15];
    float* out = (float*)d_out;

    float *h0, *h1, *wh;
    cudaGetSymbolAddress((void**)&h0, g_h0);
    cudaGetSymbolAddress((void**)&h1, g_h1);
    cudaGetSymbolAddress((void**)&wh, g_wh);

    cudaFuncSetAttribute(gat_attn_mma, cudaFuncAttributeMaxDynamicSharedMemorySize,
                         ATTN_SMEM_BYTES);

    embed_kernel<<<BATCH * NNODE / 8, 256>>>(ego, nbr, node_w, node_b, node_g, node_bb,
                                             ego_w, ego_b, ego_g, ego_bb);
    adj_kernel<<<dim3(NNODE / 32, 32, BATCH), 256>>>();

    long long hsz = (long long)BATCH * NNODE * DIM;
    if ((long long)out_size > hsz) {
        long long tail = (long long)out_size - hsz;
        int blocks = (int)((tail + 255) / 256);
        zero_tail_kernel<<<blocks, 256>>>(out, hsz, (long long)out_size);
    }

    dim3 ggrid(BATCH * NNODE / 128, 4);
    float* hbuf[2] = { h0, h1 };
    for (int l = 0; l < 2; l++) {
        tgemm256<false><<<ggrid, 256>>>(hbuf[l], gat_w + (long long)l * DIM * DIM, nullptr, wh);
        sad_kernel<<<BATCH * NNODE / 8, 256>>>(wh, gat_asrc + l * HEADS * 64,
                                               gat_adst + l * HEADS * 64);
        asmax_kernel<<<BATCH * HEADS, 256>>>();
        gat_attn_mma<<<dim3(8, HEADS, BATCH), 128, ATTN_SMEM_BYTES>>>(
            wh, gat_b + l * DIM, hbuf[1 - l]);
    }
    tgemm256<true><<<ggrid, 256>>>(h0, proj_w, proj_b, out);
}

// round 6
// speedup vs baseline: 2.2769x; 1.0418x over previous
#include <cuda_runtime.h>
#include <cstdint>

#define BATCH 16
#define NNODE 1024
#define DIM 256
#define HEADS 4
#define NBR 1023
#define TSTEPS 20

// ---------------- scratch (device globals; no allocation allowed) ----------------
__device__ float g_h0[BATCH * NNODE * DIM];
__device__ float g_h1[BATCH * NNODE * DIM];
__device__ float g_wh[BATCH * NNODE * DIM];
__device__ float g_pos[BATCH * NNODE * 2];
__device__ float g_as[BATCH * HEADS * NNODE];
__device__ float g_ad[BATCH * HEADS * NNODE];
__device__ float g_asmax[BATCH * HEADS];
__device__ uint32_t g_adjT[BATCH * 32 * NNODE];   // [b][jword][i] bit lane = j%32

// ======================= tf32 mma.sync helpers =======================
__device__ __forceinline__ uint32_t tf32r(float x) {
    uint32_t r;
    asm("cvt.rna.tf32.f32 %0, %1;" : "=r"(r) : "f"(x));
    return r;
}
__device__ __forceinline__ void mma_tf32(float* c, uint32_t a0, uint32_t a1,
                                         uint32_t a2, uint32_t a3,
                                         uint32_t b0, uint32_t b1) {
    asm volatile(
        "mma.sync.aligned.m16n8k8.row.col.f32.tf32.tf32.f32 "
        "{%0,%1,%2,%3}, {%4,%5,%6,%7}, {%8,%9}, {%0,%1,%2,%3};"
        : "+f"(c[0]), "+f"(c[1]), "+f"(c[2]), "+f"(c[3])
        : "r"(a0), "r"(a1), "r"(a2), "r"(a3), "r"(b0), "r"(b1));
}

// ---------------- embed: 8 nodes per block, weight col in regs ----------------
__global__ __launch_bounds__(256) void embed_kernel(
    const float* __restrict__ ego, const float* __restrict__ nbr,
    const float* __restrict__ node_w, const float* __restrict__ node_b,
    const float* __restrict__ node_g, const float* __restrict__ node_bb,
    const float* __restrict__ ego_w, const float* __restrict__ ego_b,
    const float* __restrict__ ego_g, const float* __restrict__ ego_bb)
{
    int t = threadIdx.x;
    int bn0 = blockIdx.x * 8;
    __shared__ float f[8][5];
    __shared__ float ws[8][8], wq[8][8];
    if (t < 40) {
        int nn = t / 5, k = t - nn * 5;
        int bn = bn0 + nn;
        int b = bn >> 10, n = bn & 1023;
        float v = (n == 0) ? ego[(b * TSTEPS + TSTEPS - 1) * 7 + k]
                           : nbr[((b * NBR + (n - 1)) * TSTEPS + TSTEPS - 1) * 11 + k];
        f[nn][k] = v;
        if (k < 2) g_pos[bn * 2 + k] = v;
    }
    __syncthreads();
    float wn[5];
#pragma unroll
    for (int k = 0; k < 5; k++) wn[k] = node_w[k * DIM + t];
    float nb = node_b[t];
    int lane = t & 31, w = t >> 5;
    float vv[8];
#pragma unroll
    for (int nn = 0; nn < 8; nn++) {
        int n = (bn0 + nn) & 1023;
        float v;
        if (n == 0) {
            v = ego_b[t];
#pragma unroll
            for (int k = 0; k < 5; k++) v = fmaf(f[nn][k], ego_w[k * DIM + t], v);
        } else {
            v = nb;
#pragma unroll
            for (int k = 0; k < 5; k++) v = fmaf(f[nn][k], wn[k], v);
        }
        v = fmaxf(v, 0.f);
        vv[nn] = v;
        float s = v, q = v * v;
#pragma unroll
        for (int o = 16; o; o >>= 1) {
            s += __shfl_down_sync(0xffffffffu, s, o);
            q += __shfl_down_sync(0xffffffffu, q, o);
        }
        if (lane == 0) { ws[nn][w] = s; wq[nn][w] = q; }
    }
    __syncthreads();
    float ng = node_g[t], nbb = node_bb[t];
#pragma unroll
    for (int nn = 0; nn < 8; nn++) {
        int bn = bn0 + nn;
        int n = bn & 1023;
        float sum = 0.f, sq = 0.f;
#pragma unroll
        for (int i = 0; i < 8; i++) { sum += ws[nn][i]; sq += wq[nn][i]; }
        float mean = sum * (1.f / 256.f);
        float var = fmaxf(sq * (1.f / 256.f) - mean * mean, 0.f);
        float inv = rsqrtf(var + 1e-5f);
        float gg = ng, bb2 = nbb;
        if (n == 0) { gg = ego_g[t]; bb2 = ego_bb[t]; }
        g_h0[(size_t)bn * DIM + t] = (vv[nn] - mean) * inv * gg + bb2;
    }
}

// ---------------- adjacency bitmask: g_adjT[b][jw][i], bit l = adj(i, jw*32+l) ----
__global__ __launch_bounds__(256) void adj_kernel()
{
    int b = blockIdx.z, jw = blockIdx.y;
    int lane = threadIdx.x & 31, w = threadIdx.x >> 5;
    int j = jw * 32 + lane;
    float2 pj = ((const float2*)g_pos)[b * NNODE + j];
    int i0 = blockIdx.x * 32 + w;
#pragma unroll
    for (int q = 0; q < 4; q++) {
        int i = i0 + q * 8;
        float2 pi = ((const float2*)g_pos)[b * NNODE + i];
        float dx = pj.x - pi.x, dy = pj.y - pi.y;
        bool a = (fmaf(dx, dx, dy * dy) < 2500.f) || (i == j);
        uint32_t word = __ballot_sync(0xffffffffu, a);
        if (lane == 0) g_adjT[(b * 32 + jw) * NNODE + i] = word;
    }
}

// ---------------- tf32 tensor-core GEMM, double-buffered smem ----------------
#define GA_STRIDE 36
#define GB_STRIDE 72
#define GEMM_AS_FLOATS (128 * GA_STRIDE)
#define GEMM_BS_FLOATS (32 * GB_STRIDE)
#define GEMM_SMEM_BYTES ((2 * GEMM_AS_FLOATS + 2 * GEMM_BS_FLOATS) * 4)
template <bool BIAS>
__global__ __launch_bounds__(256) void tgemm256(
    const float* __restrict__ A, const float* __restrict__ W,
    const float* __restrict__ bias, float* __restrict__ C)
{
    extern __shared__ float ts[];
    float* Asb[2] = { ts, ts + GEMM_AS_FLOATS };
    float* Bsb[2] = { ts + 2 * GEMM_AS_FLOATS, ts + 2 * GEMM_AS_FLOATS + GEMM_BS_FLOATS };
    int tid = threadIdx.x, w = tid >> 5, lane = tid & 31;
    int g4 = lane >> 2, q4 = lane & 3;
    int m0 = blockIdx.x * 128, n0 = blockIdx.y * 64;
    int wm = w & 3, wn = w >> 2;
    int r0 = wm * 32, c0 = wn * 32;

    int af4 = tid & 7, arow = tid >> 3;
    int bf4 = tid & 15, brow = tid >> 4;
    const float* Ag = A + (size_t)(m0 + arow) * 256 + af4 * 4;
    const float* Wg = W + (size_t)brow * 256 + n0 + bf4 * 4;

    float acc[2][4][4];
#pragma unroll
    for (int mt = 0; mt < 2; mt++)
#pragma unroll
        for (int nt = 0; nt < 4; nt++)
#pragma unroll
            for (int k = 0; k < 4; k++) acc[mt][nt][k] = 0.f;

    float4 pa[4], pb[2];
#pragma unroll
    for (int q = 0; q < 4; q++) pa[q] = *(const float4*)(Ag + (size_t)q * 32 * 256);
#pragma unroll
    for (int q = 0; q < 2; q++) pb[q] = *(const float4*)(Wg + (size_t)q * 16 * 256);
    // store chunk 0 into buffer 0
#pragma unroll
    for (int q = 0; q < 4; q++) {
        float* d = Asb[0] + (arow + q * 32) * GA_STRIDE + af4 * 4;
        d[0] = __uint_as_float(tf32r(pa[q].x));
        d[1] = __uint_as_float(tf32r(pa[q].y));
        d[2] = __uint_as_float(tf32r(pa[q].z));
        d[3] = __uint_as_float(tf32r(pa[q].w));
    }
#pragma unroll
    for (int q = 0; q < 2; q++) {
        float* d = Bsb[0] + (brow + q * 16) * GB_STRIDE + bf4 * 4;
        d[0] = __uint_as_float(tf32r(pb[q].x));
        d[1] = __uint_as_float(tf32r(pb[q].y));
        d[2] = __uint_as_float(tf32r(pb[q].z));
        d[3] = __uint_as_float(tf32r(pb[q].w));
    }
    __syncthreads();

    for (int kc = 0; kc < 8; kc++) {
        int cur = kc & 1;
        if (kc < 7) {
            const float* Agn = Ag + (kc + 1) * 32;
            const float* Wgn = Wg + (size_t)(kc + 1) * 32 * 256;
#pragma unroll
            for (int q = 0; q < 4; q++) pa[q] = *(const float4*)(Agn + (size_t)q * 32 * 256);
#pragma unroll
            for (int q = 0; q < 2; q++) pb[q] = *(const float4*)(Wgn + (size_t)q * 16 * 256);
        }
        const float* As = Asb[cur];
        const float* Bs = Bsb[cur];
#pragma unroll
        for (int kb = 0; kb < 4; kb++) {
            int k8 = kb * 8;
            const float* a0p = As + (r0 + g4) * GA_STRIDE + k8 + q4;
            uint32_t a00 = __float_as_uint(a0p[0]);
            uint32_t a01 = __float_as_uint(a0p[8 * GA_STRIDE]);
            uint32_t a02 = __float_as_uint(a0p[4]);
            uint32_t a03 = __float_as_uint(a0p[8 * GA_STRIDE + 4]);
            uint32_t a10 = __float_as_uint(a0p[16 * GA_STRIDE]);
            uint32_t a11 = __float_as_uint(a0p[24 * GA_STRIDE]);
            uint32_t a12 = __float_as_uint(a0p[16 * GA_STRIDE + 4]);
            uint32_t a13 = __float_as_uint(a0p[24 * GA_STRIDE + 4]);
            const float* bp = Bs + (k8 + q4) * GB_STRIDE + c0 + g4;
#pragma unroll
            for (int nt = 0; nt < 4; nt++) {
                uint32_t b0 = __float_as_uint(bp[nt * 8]);
                uint32_t b1 = __float_as_uint(bp[nt * 8 + 4 * GB_STRIDE]);
                mma_tf32(acc[0][nt], a00, a01, a02, a03, b0, b1);
                mma_tf32(acc[1][nt], a10, a11, a12, a13, b0, b1);
            }
        }
        if (kc < 7) {
            int nxt = cur ^ 1;
#pragma unroll
            for (int q = 0; q < 4; q++) {
                float* d = Asb[nxt] + (arow + q * 32) * GA_STRIDE + af4 * 4;
                d[0] = __uint_as_float(tf32r(pa[q].x));
                d[1] = __uint_as_float(tf32r(pa[q].y));
                d[2] = __uint_as_float(tf32r(pa[q].z));
                d[3] = __uint_as_float(tf32r(pa[q].w));
            }
#pragma unroll
            for (int q = 0; q < 2; q++) {
                float* d = Bsb[nxt] + (brow + q * 16) * GB_STRIDE + bf4 * 4;
                d[0] = __uint_as_float(tf32r(pb[q].x));
                d[1] = __uint_as_float(tf32r(pb[q].y));
                d[2] = __uint_as_float(tf32r(pb[q].z));
                d[3] = __uint_as_float(tf32r(pb[q].w));
            }
        }
        __syncthreads();
    }
#pragma unroll
    for (int mt = 0; mt < 2; mt++) {
        int row = m0 + r0 + mt * 16 + g4;
        float* c0p = C + (size_t)row * 256 + n0 + c0;
        float* c1p = c0p + 8 * 256;
#pragma unroll
        for (int nt = 0; nt < 4; nt++) {
            int cc = nt * 8 + q4 * 2;
            float bx = 0.f, by = 0.f;
            if (BIAS) { bx = bias[n0 + c0 + cc]; by = bias[n0 + c0 + cc + 1]; }
            float2 u0, u1;
            u0.x = acc[mt][nt][0] + bx; u0.y = acc[mt][nt][1] + by;
            u1.x = acc[mt][nt][2] + bx; u1.y = acc[mt][nt][3] + by;
            *(float2*)(c0p + cc) = u0;
            *(float2*)(c1p + cc) = u1;
        }
    }
}

// ---------------- a_src / a_dst per (b,n,h) ----------------
__global__ __launch_bounds__(256) void sad_kernel(
    const float* __restrict__ wh,
    const float* __restrict__ asrc, const float* __restrict__ adst)
{
    int gw = (blockIdx.x * 256 + threadIdx.x) >> 5;
    int lane = threadIdx.x & 31;
    if (gw >= BATCH * NNODE) return;
    int b = gw >> 10, n = gw & 1023;
    const float* row = wh + (long long)gw * DIM;
#pragma unroll
    for (int h = 0; h < HEADS; h++) {
        float x0 = row[h * 64 + lane], x1 = row[h * 64 + 32 + lane];
        float s = x0 * asrc[h * 64 + lane] + x1 * asrc[h * 64 + 32 + lane];
        float d = x0 * adst[h * 64 + lane] + x1 * adst[h * 64 + 32 + lane];
#pragma unroll
        for (int o = 16; o; o >>= 1) {
            s += __shfl_down_sync(0xffffffffu, s, o);
            d += __shfl_down_sync(0xffffffffu, d, o);
        }
        if (lane == 0) {
            g_as[(b * HEADS + h) * NNODE + n] = s;
            g_ad[(b * HEADS + h) * NNODE + n] = d;
        }
    }
}

__global__ __launch_bounds__(256) void asmax_kernel()
{
    int bh = blockIdx.x;
    __shared__ float sm[256];
    float m = -1e30f;
    for (int j = threadIdx.x; j < NNODE; j += 256) m = fmaxf(m, g_as[bh * NNODE + j]);
    sm[threadIdx.x] = m;
    __syncthreads();
    for (int o = 128; o; o >>= 1) {
        if (threadIdx.x < o) sm[threadIdx.x] = fmaxf(sm[threadIdx.x], sm[threadIdx.x + o]);
        __syncthreads();
    }
    if (threadIdx.x == 0) g_asmax[bh] = sm[0];
}

// ---------------- GAT attention: register-P tf32 mma.sync ----------------
// Block: (128-row i-tile, head, batch), 128 threads = 4 warps x 32 rows.
// D[128 x 72] = P[128 x 1024] @ B; B cols 0..63 = V channels, col 64 = ones (Z).
// P computed directly into A-fragments: p = adj & (t>0 ? E1[j]*F1[row] : E2[j]*F2[row]).
#define V_STRIDE 72
__global__ __launch_bounds__(128, 4) void gat_attn_mma(
    const float* __restrict__ wh, const float* __restrict__ gbias,
    float* __restrict__ hout)
{
    __shared__ float v_sm[64 * V_STRIDE];
    __shared__ float4 je[64];            // (as_j, E1_j, E2_j, -)
    __shared__ uint32_t adj_sm[256];

    int tid = threadIdx.x, w = tid >> 5, lane = tid & 31;
    int g4 = lane >> 2, q4 = lane & 3;
    int it = blockIdx.x, hh = blockIdx.y, b = blockIdx.z;
    int i0 = it * 128, bh = b * HEADS + hh;
    int r0 = w * 32;

    // per-lane row constants: rows i0 + r0 + t*8 + g4, t = 0..3
    float F1[4], F2[4], adreg[4];
    {
        float mx = g_asmax[bh];
#pragma unroll
        for (int t = 0; t < 4; t++) {
            float ad = g_ad[bh * NNODE + i0 + r0 + t * 8 + g4];
            adreg[t] = ad;
            float mm = mx + ad;
            float mr = fmaxf(mm, 0.2f * mm);
            F1[t] = __expf(ad - mr);
            F2[t] = __expf(0.2f * ad - mr);
        }
    }
    // B cols 64..71: col 64 = ones (Z), rest zeros
#pragma unroll
    for (int q = 0; q < 4; q++) {
        int idx = q * 128 + tid;
        int jr = idx >> 3, cc = 64 + (idx & 7);
        v_sm[jr * V_STRIDE + cc] = (cc == 64) ? 1.f : 0.f;
    }

    float acc[2][9][4];
#pragma unroll
    for (int mt = 0; mt < 2; mt++)
#pragma unroll
        for (int n = 0; n < 9; n++)
#pragma unroll
            for (int k = 0; k < 4; k++) acc[mt][n][k] = 0.f;

    const float* whb = wh + ((size_t)(b * NNODE)) * DIM + hh * 64;
    const uint32_t* adjb = g_adjT + (size_t)b * 32 * NNODE + i0;

    for (int ch = 0; ch < 16; ch++) {
        int j0 = ch * 64;
        __syncthreads();
        // V chunk [64 x 64] -> v_sm (tf32-rounded)
#pragma unroll
        for (int q = 0; q < 8; q++) {
            int idx = q * 128 + tid;
            int jr = idx >> 4, cc = (idx & 15) * 4;
            float4 v = *(const float4*)(whb + (size_t)(j0 + jr) * DIM + cc);
            float* dst = v_sm + jr * V_STRIDE + cc;
            dst[0] = __uint_as_float(tf32r(v.x));
            dst[1] = __uint_as_float(tf32r(v.y));
            dst[2] = __uint_as_float(tf32r(v.z));
            dst[3] = __uint_as_float(tf32r(v.w));
        }
        if (tid < 64) {
            float a = g_as[bh * NNODE + j0 + tid];
            je[tid] = make_float4(a, __expf(a), __expf(0.2f * a), 0.f);
        }
        adj_sm[tid] = adjb[(size_t)(2 * ch) * NNODE + tid];
        adj_sm[128 + tid] = adjb[(size_t)(2 * ch + 1) * NNODE + tid];
        __syncthreads();
        // adjacency words for this lane's 4 rows, both j-halves
        uint32_t Aw[2][4];
#pragma unroll
        for (int t = 0; t < 4; t++) {
            Aw[0][t] = adj_sm[r0 + t * 8 + g4];
            Aw[1][t] = adj_sm[128 + r0 + t * 8 + g4];
        }
#pragma unroll
        for (int kb = 0; kb < 8; kb++) {
            int jA = kb * 8 + q4;
            float4 jA4 = je[jA];
            float4 jB4 = je[jA + 4];
            int half = kb >> 2;
            int sh = jA & 31;            // bit position of jA; jB bit = sh+4 (sh <= 27)
            uint32_t fr[2][4];
#pragma unroll
            for (int t = 0; t < 4; t++) {
                uint32_t Aword = Aw[half][t];
                uint32_t mA = (uint32_t)(((int32_t)(Aword << (31 - sh))) >> 31);
                uint32_t mB = (uint32_t)(((int32_t)(Aword << (27 - sh))) >> 31);
                float tA = jA4.x + adreg[t];
                float tB = jB4.x + adreg[t];
                float pA = (tA > 0.f) ? jA4.y * F1[t] : jA4.z * F2[t];
                float pB = (tB > 0.f) ? jB4.y * F1[t] : jB4.z * F2[t];
                fr[t >> 1][t & 1] = __float_as_uint(pA) & mA;
                fr[t >> 1][2 + (t & 1)] = __float_as_uint(pB) & mB;
            }
            const float* bp = v_sm + (kb * 8 + q4) * V_STRIDE + g4;
#pragma unroll
            for (int nt = 0; nt < 9; nt++) {
                uint32_t b0 = __float_as_uint(bp[nt * 8]);
                uint32_t b1 = __float_as_uint(bp[nt * 8 + 4 * V_STRIDE]);
                mma_tf32(acc[0][nt], fr[0][0], fr[0][1], fr[0][2], fr[0][3], b0, b1);
                mma_tf32(acc[1][nt], fr[1][0], fr[1][1], fr[1][2], fr[1][3], b0, b1);
            }
        }
    }
    // ---- epilogue: Z in n-tile 8 col 64 (q4==0 lanes), bcast via shfl ----
    const float* bp = gbias + hh * 64;
#pragma unroll
    for (int mt = 0; mt < 2; mt++) {
        float z0 = __shfl_sync(0xffffffffu, acc[mt][8][0], lane & 28);
        float z1 = __shfl_sync(0xffffffffu, acc[mt][8][2], lane & 28);
        float iz0 = 1.f / z0;
        float iz1 = 1.f / z1;
        int rowg = i0 + r0 + mt * 16 + g4;
        float* o0 = hout + ((size_t)(b * NNODE) + rowg) * DIM + hh * 64;
        float* o1 = o0 + 8 * DIM;
#pragma unroll
        for (int nt = 0; nt < 8; nt++) {
            int cc = nt * 8 + q4 * 2;
            float bx = bp[cc], by = bp[cc + 1];
            float2 u0, u1;
            u0.x = fmaxf(fmaf(acc[mt][nt][0], iz0, bx), 0.f);
            u0.y = fmaxf(fmaf(acc[mt][nt][1], iz0, by), 0.f);
            u1.x = fmaxf(fmaf(acc[mt][nt][2], iz1, bx), 0.f);
            u1.y = fmaxf(fmaf(acc[mt][nt][3], iz1, by), 0.f);
            *(float2*)(o0 + cc) = u0;
            *(float2*)(o1 + cc) = u1;
        }
    }
}

// ---------------- zero tail of output (mask = all false) ----------------
__global__ void zero_tail_kernel(float* out, long long start, long long total)
{
    long long i = start + (long long)blockIdx.x * blockDim.x + threadIdx.x;
    if (i < total) out[i] = 0.f;
}

// ---------------- launch ----------------
extern "C" void kernel_launch(void* const* d_in, const int* in_sizes, int n_in,
                              void* d_out, int out_size)
{
    const float* ego      = (const float*)d_in[0];
    const float* nbr      = (const float*)d_in[1];
    const float* node_w   = (const float*)d_in[2];
    const float* node_b   = (const float*)d_in[3];
    const float* node_g   = (const float*)d_in[4];
    const float* node_bb  = (const float*)d_in[5];
    const float* ego_w    = (const float*)d_in[6];
    const float* ego_b    = (const float*)d_in[7];
    const float* ego_g    = (const float*)d_in[8];
    const float* ego_bb   = (const float*)d_in[9];
    const float* gat_w    = (const float*)d_in[10];
    const float* gat_asrc = (const float*)d_in[11];
    const float* gat_adst = (const float*)d_in[12];
    const float* gat_b    = (const float*)d_in[13];
    const float* proj_w   = (const float*)d_in[14];
    const float* proj_b   = (const float*)d_in[15];
    float* out = (float*)d_out;

    float *h0, *h1, *wh;
    cudaGetSymbolAddress((void**)&h0, g_h0);
    cudaGetSymbolAddress((void**)&h1, g_h1);
    cudaGetSymbolAddress((void**)&wh, g_wh);

    cudaFuncSetAttribute(tgemm256<false>, cudaFuncAttributeMaxDynamicSharedMemorySize,
                         GEMM_SMEM_BYTES);
    cudaFuncSetAttribute(tgemm256<true>, cudaFuncAttributeMaxDynamicSharedMemorySize,
                         GEMM_SMEM_BYTES);

    embed_kernel<<<BATCH * NNODE / 8, 256>>>(ego, nbr, node_w, node_b, node_g, node_bb,
                                             ego_w, ego_b, ego_g, ego_bb);
    adj_kernel<<<dim3(NNODE / 32, 32, BATCH), 256>>>();

    long long hsz = (long long)BATCH * NNODE * DIM;
    if ((long long)out_size > hsz) {
        long long tail = (long long)out_size - hsz;
        int blocks = (int)((tail + 255) / 256);
        zero_tail_kernel<<<blocks, 256>>>(out, hsz, (long long)out_size);
    }

    dim3 ggrid(BATCH * NNODE / 128, 4);
    float* hbuf[2] = { h0, h1 };
    for (int l = 0; l < 2; l++) {
        tgemm256<false><<<ggrid, 256, GEMM_SMEM_BYTES>>>(hbuf[l],
            gat_w + (long long)l * DIM * DIM, nullptr, wh);
        sad_kernel<<<BATCH * NNODE / 8, 256>>>(wh, gat_asrc + l * HEADS * 64,
                                               gat_adst + l * HEADS * 64);
        asmax_kernel<<<BATCH * HEADS, 256>>>();
        gat_attn_mma<<<dim3(8, HEADS, BATCH), 128>>>(wh, gat_b + l * DIM, hbuf[1 - l]);
    }
    tgemm256<true><<<ggrid, 256, GEMM_SMEM_BYTES>>>(h0, proj_w, proj_b, out);
}

// round 7
// speedup vs baseline: 2.5588x; 1.1238x over previous
#include <cuda_runtime.h>
#include <cstdint>

#define BATCH 16
#define NNODE 1024
#define DIM 256
#define HEADS 4
#define NBR 1023
#define TSTEPS 20

// ---------------- scratch (device globals; no allocation allowed) ----------------
__device__ float g_h0[BATCH * NNODE * DIM];
__device__ float g_h1[BATCH * NNODE * DIM];
__device__ float g_wh[BATCH * NNODE * DIM];
__device__ float g_pos[BATCH * NNODE * 2];
__device__ float g_as[BATCH * HEADS * NNODE];
__device__ float g_ad[BATCH * HEADS * NNODE];
__device__ float g_asmax[BATCH * HEADS];
__device__ uint32_t g_adjT[BATCH * 32 * NNODE];   // [b][jword][i] bit lane = j%32

// ======================= tf32 mma.sync helpers =======================
__device__ __forceinline__ uint32_t tf32r(float x) {
    uint32_t r;
    asm("cvt.rna.tf32.f32 %0, %1;" : "=r"(r) : "f"(x));
    return r;
}
__device__ __forceinline__ void mma_tf32(float* c, uint32_t a0, uint32_t a1,
                                         uint32_t a2, uint32_t a3,
                                         uint32_t b0, uint32_t b1) {
    asm volatile(
        "mma.sync.aligned.m16n8k8.row.col.f32.tf32.tf32.f32 "
        "{%0,%1,%2,%3}, {%4,%5,%6,%7}, {%8,%9}, {%0,%1,%2,%3};"
        : "+f"(c[0]), "+f"(c[1]), "+f"(c[2]), "+f"(c[3])
        : "r"(a0), "r"(a1), "r"(a2), "r"(a3), "r"(b0), "r"(b1));
}

// ---------------- embed: 8 nodes per block, weight col in regs ----------------
__global__ __launch_bounds__(256) void embed_kernel(
    const float* __restrict__ ego, const float* __restrict__ nbr,
    const float* __restrict__ node_w, const float* __restrict__ node_b,
    const float* __restrict__ node_g, const float* __restrict__ node_bb,
    const float* __restrict__ ego_w, const float* __restrict__ ego_b,
    const float* __restrict__ ego_g, const float* __restrict__ ego_bb)
{
    int t = threadIdx.x;
    int bn0 = blockIdx.x * 8;
    __shared__ float f[8][5];
    __shared__ float ws[8][8], wq[8][8];
    if (t < 40) {
        int nn = t / 5, k = t - nn * 5;
        int bn = bn0 + nn;
        int b = bn >> 10, n = bn & 1023;
        float v = (n == 0) ? ego[(b * TSTEPS + TSTEPS - 1) * 7 + k]
                           : nbr[((b * NBR + (n - 1)) * TSTEPS + TSTEPS - 1) * 11 + k];
        f[nn][k] = v;
        if (k < 2) g_pos[bn * 2 + k] = v;
    }
    __syncthreads();
    float wn[5];
#pragma unroll
    for (int k = 0; k < 5; k++) wn[k] = node_w[k * DIM + t];
    float nb = node_b[t];
    int lane = t & 31, w = t >> 5;
    float vv[8];
#pragma unroll
    for (int nn = 0; nn < 8; nn++) {
        int n = (bn0 + nn) & 1023;
        float v;
        if (n == 0) {
            v = ego_b[t];
#pragma unroll
            for (int k = 0; k < 5; k++) v = fmaf(f[nn][k], ego_w[k * DIM + t], v);
        } else {
            v = nb;
#pragma unroll
            for (int k = 0; k < 5; k++) v = fmaf(f[nn][k], wn[k], v);
        }
        v = fmaxf(v, 0.f);
        vv[nn] = v;
        float s = v, q = v * v;
#pragma unroll
        for (int o = 16; o; o >>= 1) {
            s += __shfl_down_sync(0xffffffffu, s, o);
            q += __shfl_down_sync(0xffffffffu, q, o);
        }
        if (lane == 0) { ws[nn][w] = s; wq[nn][w] = q; }
    }
    __syncthreads();
    float ng = node_g[t], nbb = node_bb[t];
#pragma unroll
    for (int nn = 0; nn < 8; nn++) {
        int bn = bn0 + nn;
        int n = bn & 1023;
        float sum = 0.f, sq = 0.f;
#pragma unroll
        for (int i = 0; i < 8; i++) { sum += ws[nn][i]; sq += wq[nn][i]; }
        float mean = sum * (1.f / 256.f);
        float var = fmaxf(sq * (1.f / 256.f) - mean * mean, 0.f);
        float inv = rsqrtf(var + 1e-5f);
        float gg = ng, bb2 = nbb;
        if (n == 0) { gg = ego_g[t]; bb2 = ego_bb[t]; }
        g_h0[(size_t)bn * DIM + t] = (vv[nn] - mean) * inv * gg + bb2;
    }
}

// ---------------- adjacency bitmask: g_adjT[b][jw][i], bit l = adj(i, jw*32+l) ----
__global__ __launch_bounds__(256) void adj_kernel()
{
    int b = blockIdx.z, jw = blockIdx.y;
    int lane = threadIdx.x & 31, w = threadIdx.x >> 5;
    int j = jw * 32 + lane;
    float2 pj = ((const float2*)g_pos)[b * NNODE + j];
    int i0 = blockIdx.x * 32 + w;
#pragma unroll
    for (int q = 0; q < 4; q++) {
        int i = i0 + q * 8;
        float2 pi = ((const float2*)g_pos)[b * NNODE + i];
        float dx = pj.x - pi.x, dy = pj.y - pi.y;
        bool a = (fmaf(dx, dx, dy * dy) < 2500.f) || (i == j);
        uint32_t word = __ballot_sync(0xffffffffu, a);
        if (lane == 0) g_adjT[(b * 32 + jw) * NNODE + i] = word;
    }
}

// ---------------- tf32 tensor-core GEMM (R5 single-buffer, measured 28us) ----------
#define GA_STRIDE 36
#define GB_STRIDE 72
template <bool BIAS>
__global__ __launch_bounds__(256) void tgemm256(
    const float* __restrict__ A, const float* __restrict__ W,
    const float* __restrict__ bias, float* __restrict__ C)
{
    __shared__ float As[128 * GA_STRIDE];
    __shared__ float Bs[32 * GB_STRIDE];
    int tid = threadIdx.x, w = tid >> 5, lane = tid & 31;
    int g4 = lane >> 2, q4 = lane & 3;
    int m0 = blockIdx.x * 128, n0 = blockIdx.y * 64;
    int wm = w & 3, wn = w >> 2;
    int r0 = wm * 32, c0 = wn * 32;

    int af4 = tid & 7, arow = tid >> 3;
    int bf4 = tid & 15, brow = tid >> 4;
    const float* Ag = A + (size_t)(m0 + arow) * 256 + af4 * 4;
    const float* Wg = W + (size_t)brow * 256 + n0 + bf4 * 4;

    float acc[2][4][4];
#pragma unroll
    for (int mt = 0; mt < 2; mt++)
#pragma unroll
        for (int nt = 0; nt < 4; nt++)
#pragma unroll
            for (int k = 0; k < 4; k++) acc[mt][nt][k] = 0.f;

    float4 pa[4], pb[2];
#pragma unroll
    for (int q = 0; q < 4; q++) pa[q] = *(const float4*)(Ag + (size_t)q * 32 * 256);
#pragma unroll
    for (int q = 0; q < 2; q++) pb[q] = *(const float4*)(Wg + (size_t)q * 16 * 256);

    for (int kc = 0; kc < 8; kc++) {
        __syncthreads();
#pragma unroll
        for (int q = 0; q < 4; q++) {
            float* d = As + (arow + q * 32) * GA_STRIDE + af4 * 4;
            d[0] = __uint_as_float(tf32r(pa[q].x));
            d[1] = __uint_as_float(tf32r(pa[q].y));
            d[2] = __uint_as_float(tf32r(pa[q].z));
            d[3] = __uint_as_float(tf32r(pa[q].w));
        }
#pragma unroll
        for (int q = 0; q < 2; q++) {
            float* d = Bs + (brow + q * 16) * GB_STRIDE + bf4 * 4;
            d[0] = __uint_as_float(tf32r(pb[q].x));
            d[1] = __uint_as_float(tf32r(pb[q].y));
            d[2] = __uint_as_float(tf32r(pb[q].z));
            d[3] = __uint_as_float(tf32r(pb[q].w));
        }
        __syncthreads();
        if (kc < 7) {
            const float* Agn = Ag + (kc + 1) * 32;
            const float* Wgn = Wg + (size_t)(kc + 1) * 32 * 256;
#pragma unroll
            for (int q = 0; q < 4; q++) pa[q] = *(const float4*)(Agn + (size_t)q * 32 * 256);
#pragma unroll
            for (int q = 0; q < 2; q++) pb[q] = *(const float4*)(Wgn + (size_t)q * 16 * 256);
        }
#pragma unroll
        for (int kb = 0; kb < 4; kb++) {
            int k8 = kb * 8;
            const float* a0p = As + (r0 + g4) * GA_STRIDE + k8 + q4;
            uint32_t a00 = __float_as_uint(a0p[0]);
            uint32_t a01 = __float_as_uint(a0p[8 * GA_STRIDE]);
            uint32_t a02 = __float_as_uint(a0p[4]);
            uint32_t a03 = __float_as_uint(a0p[8 * GA_STRIDE + 4]);
            uint32_t a10 = __float_as_uint(a0p[16 * GA_STRIDE]);
            uint32_t a11 = __float_as_uint(a0p[24 * GA_STRIDE]);
            uint32_t a12 = __float_as_uint(a0p[16 * GA_STRIDE + 4]);
            uint32_t a13 = __float_as_uint(a0p[24 * GA_STRIDE + 4]);
            const float* bp = Bs + (k8 + q4) * GB_STRIDE + c0 + g4;
#pragma unroll
            for (int nt = 0; nt < 4; nt++) {
                uint32_t b0 = __float_as_uint(bp[nt * 8]);
                uint32_t b1 = __float_as_uint(bp[nt * 8 + 4 * GB_STRIDE]);
                mma_tf32(acc[0][nt], a00, a01, a02, a03, b0, b1);
                mma_tf32(acc[1][nt], a10, a11, a12, a13, b0, b1);
            }
        }
    }
#pragma unroll
    for (int mt = 0; mt < 2; mt++) {
        int row = m0 + r0 + mt * 16 + g4;
        float* c0p = C + (size_t)row * 256 + n0 + c0;
        float* c1p = c0p + 8 * 256;
#pragma unroll
        for (int nt = 0; nt < 4; nt++) {
            int cc = nt * 8 + q4 * 2;
            float bx = 0.f, by = 0.f;
            if (BIAS) { bx = bias[n0 + c0 + cc]; by = bias[n0 + c0 + cc + 1]; }
            float2 u0, u1;
            u0.x = acc[mt][nt][0] + bx; u0.y = acc[mt][nt][1] + by;
            u1.x = acc[mt][nt][2] + bx; u1.y = acc[mt][nt][3] + by;
            *(float2*)(c0p + cc) = u0;
            *(float2*)(c1p + cc) = u1;
        }
    }
}

// ---------------- a_src / a_dst per (b,n,h) ----------------
__global__ __launch_bounds__(256) void sad_kernel(
    const float* __restrict__ wh,
    const float* __restrict__ asrc, const float* __restrict__ adst)
{
    int gw = (blockIdx.x * 256 + threadIdx.x) >> 5;
    int lane = threadIdx.x & 31;
    if (gw >= BATCH * NNODE) return;
    int b = gw >> 10, n = gw & 1023;
    const float* row = wh + (long long)gw * DIM;
#pragma unroll
    for (int h = 0; h < HEADS; h++) {
        float x0 = row[h * 64 + lane], x1 = row[h * 64 + 32 + lane];
        float s = x0 * asrc[h * 64 + lane] + x1 * asrc[h * 64 + 32 + lane];
        float d = x0 * adst[h * 64 + lane] + x1 * adst[h * 64 + 32 + lane];
#pragma unroll
        for (int o = 16; o; o >>= 1) {
            s += __shfl_down_sync(0xffffffffu, s, o);
            d += __shfl_down_sync(0xffffffffu, d, o);
        }
        if (lane == 0) {
            g_as[(b * HEADS + h) * NNODE + n] = s;
            g_ad[(b * HEADS + h) * NNODE + n] = d;
        }
    }
}

__global__ __launch_bounds__(256) void asmax_kernel()
{
    int bh = blockIdx.x;
    __shared__ float sm[256];
    float m = -1e30f;
    for (int j = threadIdx.x; j < NNODE; j += 256) m = fmaxf(m, g_as[bh * NNODE + j]);
    sm[threadIdx.x] = m;
    __syncthreads();
    for (int o = 128; o; o >>= 1) {
        if (threadIdx.x < o) sm[threadIdx.x] = fmaxf(sm[threadIdx.x], sm[threadIdx.x + o]);
        __syncthreads();
    }
    if (threadIdx.x == 0) g_asmax[bh] = sm[0];
}

// ---------------- GAT attention: register-P tf32 mma.sync (R6 version) ----------
#define V_STRIDE 72
__global__ __launch_bounds__(128, 4) void gat_attn_mma(
    const float* __restrict__ wh, const float* __restrict__ gbias,
    float* __restrict__ hout)
{
    __shared__ float v_sm[64 * V_STRIDE];
    __shared__ float4 je[64];            // (as_j, E1_j, E2_j, -)
    __shared__ uint32_t adj_sm[256];

    int tid = threadIdx.x, w = tid >> 5, lane = tid & 31;
    int g4 = lane >> 2, q4 = lane & 3;
    int it = blockIdx.x, hh = blockIdx.y, b = blockIdx.z;
    int i0 = it * 128, bh = b * HEADS + hh;
    int r0 = w * 32;

    float F1[4], F2[4], adreg[4];
    {
        float mx = g_asmax[bh];
#pragma unroll
        for (int t = 0; t < 4; t++) {
            float ad = g_ad[bh * NNODE + i0 + r0 + t * 8 + g4];
            adreg[t] = ad;
            float mm = mx + ad;
            float mr = fmaxf(mm, 0.2f * mm);
            F1[t] = __expf(ad - mr);
            F2[t] = __expf(0.2f * ad - mr);
        }
    }
#pragma unroll
    for (int q = 0; q < 4; q++) {
        int idx = q * 128 + tid;
        int jr = idx >> 3, cc = 64 + (idx & 7);
        v_sm[jr * V_STRIDE + cc] = (cc == 64) ? 1.f : 0.f;
    }

    float acc[2][9][4];
#pragma unroll
    for (int mt = 0; mt < 2; mt++)
#pragma unroll
        for (int n = 0; n < 9; n++)
#pragma unroll
            for (int k = 0; k < 4; k++) acc[mt][n][k] = 0.f;

    const float* whb = wh + ((size_t)(b * NNODE)) * DIM + hh * 64;
    const uint32_t* adjb = g_adjT + (size_t)b * 32 * NNODE + i0;

    for (int ch = 0; ch < 16; ch++) {
        int j0 = ch * 64;
        __syncthreads();
#pragma unroll
        for (int q = 0; q < 8; q++) {
            int idx = q * 128 + tid;
            int jr = idx >> 4, cc = (idx & 15) * 4;
            float4 v = *(const float4*)(whb + (size_t)(j0 + jr) * DIM + cc);
            float* dst = v_sm + jr * V_STRIDE + cc;
            dst[0] = __uint_as_float(tf32r(v.x));
            dst[1] = __uint_as_float(tf32r(v.y));
            dst[2] = __uint_as_float(tf32r(v.z));
            dst[3] = __uint_as_float(tf32r(v.w));
        }
        if (tid < 64) {
            float a = g_as[bh * NNODE + j0 + tid];
            je[tid] = make_float4(a, __expf(a), __expf(0.2f * a), 0.f);
        }
        adj_sm[tid] = adjb[(size_t)(2 * ch) * NNODE + tid];
        adj_sm[128 + tid] = adjb[(size_t)(2 * ch + 1) * NNODE + tid];
        __syncthreads();
        uint32_t Aw[2][4];
#pragma unroll
        for (int t = 0; t < 4; t++) {
            Aw[0][t] = adj_sm[r0 + t * 8 + g4];
            Aw[1][t] = adj_sm[128 + r0 + t * 8 + g4];
        }
#pragma unroll
        for (int kb = 0; kb < 8; kb++) {
            int jA = kb * 8 + q4;
            float4 jA4 = je[jA];
            float4 jB4 = je[jA + 4];
            int half = kb >> 2;
            int sh = jA & 31;
            uint32_t fr[2][4];
#pragma unroll
            for (int t = 0; t < 4; t++) {
                uint32_t Aword = Aw[half][t];
                uint32_t mA = (uint32_t)(((int32_t)(Aword << (31 - sh))) >> 31);
                uint32_t mB = (uint32_t)(((int32_t)(Aword << (27 - sh))) >> 31);
                float tA = jA4.x + adreg[t];
                float tB = jB4.x + adreg[t];
                float pA = (tA > 0.f) ? jA4.y * F1[t] : jA4.z * F2[t];
                float pB = (tB > 0.f) ? jB4.y * F1[t] : jB4.z * F2[t];
                fr[t >> 1][t & 1] = __float_as_uint(pA) & mA;
                fr[t >> 1][2 + (t & 1)] = __float_as_uint(pB) & mB;
            }
            const float* bp = v_sm + (kb * 8 + q4) * V_STRIDE + g4;
#pragma unroll
            for (int nt = 0; nt < 9; nt++) {
                uint32_t b0 = __float_as_uint(bp[nt * 8]);
                uint32_t b1 = __float_as_uint(bp[nt * 8 + 4 * V_STRIDE]);
                mma_tf32(acc[0][nt], fr[0][0], fr[0][1], fr[0][2], fr[0][3], b0, b1);
                mma_tf32(acc[1][nt], fr[1][0], fr[1][1], fr[1][2], fr[1][3], b0, b1);
            }
        }
    }
    const float* bp = gbias + hh * 64;
#pragma unroll
    for (int mt = 0; mt < 2; mt++) {
        float z0 = __shfl_sync(0xffffffffu, acc[mt][8][0], lane & 28);
        float z1 = __shfl_sync(0xffffffffu, acc[mt][8][2], lane & 28);
        float iz0 = 1.f / z0;
        float iz1 = 1.f / z1;
        int rowg = i0 + r0 + mt * 16 + g4;
        float* o0 = hout + ((size_t)(b * NNODE) + rowg) * DIM + hh * 64;
        float* o1 = o0 + 8 * DIM;
#pragma unroll
        for (int nt = 0; nt < 8; nt++) {
            int cc = nt * 8 + q4 * 2;
            float bx = bp[cc], by = bp[cc + 1];
            float2 u0, u1;
            u0.x = fmaxf(fmaf(acc[mt][nt][0], iz0, bx), 0.f);
            u0.y = fmaxf(fmaf(acc[mt][nt][1], iz0, by), 0.f);
            u1.x = fmaxf(fmaf(acc[mt][nt][2], iz1, bx), 0.f);
            u1.y = fmaxf(fmaf(acc[mt][nt][3], iz1, by), 0.f);
            *(float2*)(o0 + cc) = u0;
            *(float2*)(o1 + cc) = u1;
        }
    }
}

// ---------------- zero tail of output (mask = all false) ----------------
__global__ void zero_tail_kernel(float* out, long long start, long long total)
{
    long long i = start + (long long)blockIdx.x * blockDim.x + threadIdx.x;
    if (i < total) out[i] = 0.f;
}

// ---------------- launch ----------------
extern "C" void kernel_launch(void* const* d_in, const int* in_sizes, int n_in,
                              void* d_out, int out_size)
{
    const float* ego      = (const float*)d_in[0];
    const float* nbr      = (const float*)d_in[1];
    const float* node_w   = (const float*)d_in[2];
    const float* node_b   = (const float*)d_in[3];
    const float* node_g   = (const float*)d_in[4];
    const float* node_bb  = (const float*)d_in[5];
    const float* ego_w    = (const float*)d_in[6];
    const float* ego_b    = (const float*)d_in[7];
    const float* ego_g    = (const float*)d_in[8];
    const float* ego_bb   = (const float*)d_in[9];
    const float* gat_w    = (const float*)d_in[10];
    const float* gat_asrc = (const float*)d_in[11];
    const float* gat_adst = (const float*)d_in[12];
    const float* gat_b    = (const float*)d_in[13];
    const float* proj_w   = (const float*)d_in[14];
    const float* proj_b   = (const float*)d_in[15];
    float* out = (float*)d_out;

    float *h0, *h1, *wh;
    cudaGetSymbolAddress((void**)&h0, g_h0);
    cudaGetSymbolAddress((void**)&h1, g_h1);
    cudaGetSymbolAddress((void**)&wh, g_wh);

    embed_kernel<<<BATCH * NNODE / 8, 256>>>(ego, nbr, node_w, node_b, node_g, node_bb,
                                             ego_w, ego_b, ego_g, ego_bb);
    adj_kernel<<<dim3(NNODE / 32, 32, BATCH), 256>>>();

    long long hsz = (long long)BATCH * NNODE * DIM;
    if ((long long)out_size > hsz) {
        long long tail = (long long)out_size - hsz;
        int blocks = (int)((tail + 255) / 256);
        zero_tail_kernel<<<blocks, 256>>>(out, hsz, (long long)out_size);
    }

    dim3 ggrid(BATCH * NNODE / 128, 4);
    float* hbuf[2] = { h0, h1 };
    for (int l = 0; l < 2; l++) {
        tgemm256<false><<<ggrid, 256>>>(hbuf[l], gat_w + (long long)l * DIM * DIM,
                                        nullptr, wh);
        sad_kernel<<<BATCH * NNODE / 8, 256>>>(wh, gat_asrc + l * HEADS * 64,
                                               gat_adst + l * HEADS * 64);
        asmax_kernel<<<BATCH * HEADS, 256>>>();
        gat_attn_mma<<<dim3(8, HEADS, BATCH), 128>>>(wh, gat_b + l * DIM, hbuf[1 - l]);
    }
    tgemm256<true><<<ggrid, 256>>>(h0, proj_w, proj_b, out);
}

// round 8
// speedup vs baseline: 2.8064x; 1.0967x over previous
#include <cuda_runtime.h>
#include <cstdint>

#define BATCH 16
#define NNODE 1024
#define DIM 256
#define HEADS 4
#define NBR 1023
#define TSTEPS 20

// ---------------- scratch (device globals; no allocation allowed) ----------------
__device__ float g_h0[BATCH * NNODE * DIM];
__device__ float g_h1[BATCH * NNODE * DIM];
__device__ float g_wh[BATCH * NNODE * DIM];
__device__ float g_pos[BATCH * NNODE * 2];
__device__ float g_as[BATCH * HEADS * NNODE];
__device__ float g_ad[BATCH * HEADS * NNODE];
__device__ float g_asmax[BATCH * HEADS];
__device__ uint32_t g_adjT[BATCH * 32 * NNODE];   // [b][jword][i] bit lane = j%32

// ======================= tf32 mma.sync helpers =======================
__device__ __forceinline__ uint32_t tf32r(float x) {
    uint32_t r;
    asm("cvt.rna.tf32.f32 %0, %1;" : "=r"(r) : "f"(x));
    return r;
}
__device__ __forceinline__ void mma_tf32(float* c, uint32_t a0, uint32_t a1,
                                         uint32_t a2, uint32_t a3,
                                         uint32_t b0, uint32_t b1) {
    asm volatile(
        "mma.sync.aligned.m16n8k8.row.col.f32.tf32.tf32.f32 "
        "{%0,%1,%2,%3}, {%4,%5,%6,%7}, {%8,%9}, {%0,%1,%2,%3};"
        : "+f"(c[0]), "+f"(c[1]), "+f"(c[2]), "+f"(c[3])
        : "r"(a0), "r"(a1), "r"(a2), "r"(a3), "r"(b0), "r"(b1));
}

// ---------------- embed: 8 nodes per block, weight col in regs ----------------
__global__ __launch_bounds__(256) void embed_kernel(
    const float* __restrict__ ego, const float* __restrict__ nbr,
    const float* __restrict__ node_w, const float* __restrict__ node_b,
    const float* __restrict__ node_g, const float* __restrict__ node_bb,
    const float* __restrict__ ego_w, const float* __restrict__ ego_b,
    const float* __restrict__ ego_g, const float* __restrict__ ego_bb)
{
    int t = threadIdx.x;
    int bn0 = blockIdx.x * 8;
    __shared__ float f[8][5];
    __shared__ float ws[8][8], wq[8][8];
    if (t < 40) {
        int nn = t / 5, k = t - nn * 5;
        int bn = bn0 + nn;
        int b = bn >> 10, n = bn & 1023;
        float v = (n == 0) ? ego[(b * TSTEPS + TSTEPS - 1) * 7 + k]
                           : nbr[((b * NBR + (n - 1)) * TSTEPS + TSTEPS - 1) * 11 + k];
        f[nn][k] = v;
        if (k < 2) g_pos[bn * 2 + k] = v;
    }
    __syncthreads();
    float wn[5];
#pragma unroll
    for (int k = 0; k < 5; k++) wn[k] = node_w[k * DIM + t];
    float nb = node_b[t];
    int lane = t & 31, w = t >> 5;
    float vv[8];
#pragma unroll
    for (int nn = 0; nn < 8; nn++) {
        int n = (bn0 + nn) & 1023;
        float v;
        if (n == 0) {
            v = ego_b[t];
#pragma unroll
            for (int k = 0; k < 5; k++) v = fmaf(f[nn][k], ego_w[k * DIM + t], v);
        } else {
            v = nb;
#pragma unroll
            for (int k = 0; k < 5; k++) v = fmaf(f[nn][k], wn[k], v);
        }
        v = fmaxf(v, 0.f);
        vv[nn] = v;
        float s = v, q = v * v;
#pragma unroll
        for (int o = 16; o; o >>= 1) {
            s += __shfl_down_sync(0xffffffffu, s, o);
            q += __shfl_down_sync(0xffffffffu, q, o);
        }
        if (lane == 0) { ws[nn][w] = s; wq[nn][w] = q; }
    }
    __syncthreads();
    float ng = node_g[t], nbb = node_bb[t];
#pragma unroll
    for (int nn = 0; nn < 8; nn++) {
        int bn = bn0 + nn;
        int n = bn & 1023;
        float sum = 0.f, sq = 0.f;
#pragma unroll
        for (int i = 0; i < 8; i++) { sum += ws[nn][i]; sq += wq[nn][i]; }
        float mean = sum * (1.f / 256.f);
        float var = fmaxf(sq * (1.f / 256.f) - mean * mean, 0.f);
        float inv = rsqrtf(var + 1e-5f);
        float gg = ng, bb2 = nbb;
        if (n == 0) { gg = ego_g[t]; bb2 = ego_bb[t]; }
        g_h0[(size_t)bn * DIM + t] = (vv[nn] - mean) * inv * gg + bb2;
    }
}

// ---------------- adjacency bitmask ----------------
__global__ __launch_bounds__(256) void adj_kernel()
{
    int b = blockIdx.z, jw = blockIdx.y;
    int lane = threadIdx.x & 31, w = threadIdx.x >> 5;
    int j = jw * 32 + lane;
    float2 pj = ((const float2*)g_pos)[b * NNODE + j];
    int i0 = blockIdx.x * 32 + w;
#pragma unroll
    for (int q = 0; q < 4; q++) {
        int i = i0 + q * 8;
        float2 pi = ((const float2*)g_pos)[b * NNODE + i];
        float dx = pj.x - pi.x, dy = pj.y - pi.y;
        bool a = (fmaf(dx, dx, dy * dy) < 2500.f) || (i == j);
        uint32_t word = __ballot_sync(0xffffffffu, a);
        if (lane == 0) g_adjT[(b * 32 + jw) * NNODE + i] = word;
    }
}

// ---------------- tf32 tensor-core GEMM (+fused a_src/a_dst in epilogue) ----------
#define GA_STRIDE 36
#define GB_STRIDE 72
template <bool BIAS, bool SAD>
__global__ __launch_bounds__(256) void tgemm256(
    const float* __restrict__ A, const float* __restrict__ W,
    const float* __restrict__ bias, float* __restrict__ C,
    const float* __restrict__ asrc, const float* __restrict__ adst)
{
    __shared__ float As[128 * GA_STRIDE];
    __shared__ float Bs[32 * GB_STRIDE];
    int tid = threadIdx.x, w = tid >> 5, lane = tid & 31;
    int g4 = lane >> 2, q4 = lane & 3;
    int m0 = blockIdx.x * 128, n0 = blockIdx.y * 64;
    int wm = w & 3, wn = w >> 2;
    int r0 = wm * 32, c0 = wn * 32;

    int af4 = tid & 7, arow = tid >> 3;
    int bf4 = tid & 15, brow = tid >> 4;
    const float* Ag = A + (size_t)(m0 + arow) * 256 + af4 * 4;
    const float* Wg = W + (size_t)brow * 256 + n0 + bf4 * 4;

    float acc[2][4][4];
#pragma unroll
    for (int mt = 0; mt < 2; mt++)
#pragma unroll
        for (int nt = 0; nt < 4; nt++)
#pragma unroll
            for (int k = 0; k < 4; k++) acc[mt][nt][k] = 0.f;

    float4 pa[4], pb[2];
#pragma unroll
    for (int q = 0; q < 4; q++) pa[q] = *(const float4*)(Ag + (size_t)q * 32 * 256);
#pragma unroll
    for (int q = 0; q < 2; q++) pb[q] = *(const float4*)(Wg + (size_t)q * 16 * 256);

    for (int kc = 0; kc < 8; kc++) {
        __syncthreads();
#pragma unroll
        for (int q = 0; q < 4; q++) {
            float* d = As + (arow + q * 32) * GA_STRIDE + af4 * 4;
            d[0] = __uint_as_float(tf32r(pa[q].x));
            d[1] = __uint_as_float(tf32r(pa[q].y));
            d[2] = __uint_as_float(tf32r(pa[q].z));
            d[3] = __uint_as_float(tf32r(pa[q].w));
        }
#pragma unroll
        for (int q = 0; q < 2; q++) {
            float* d = Bs + (brow + q * 16) * GB_STRIDE + bf4 * 4;
            d[0] = __uint_as_float(tf32r(pb[q].x));
            d[1] = __uint_as_float(tf32r(pb[q].y));
            d[2] = __uint_as_float(tf32r(pb[q].z));
            d[3] = __uint_as_float(tf32r(pb[q].w));
        }
        __syncthreads();
        if (kc < 7) {
            const float* Agn = Ag + (kc + 1) * 32;
            const float* Wgn = Wg + (size_t)(kc + 1) * 32 * 256;
#pragma unroll
            for (int q = 0; q < 4; q++) pa[q] = *(const float4*)(Agn + (size_t)q * 32 * 256);
#pragma unroll
            for (int q = 0; q < 2; q++) pb[q] = *(const float4*)(Wgn + (size_t)q * 16 * 256);
        }
#pragma unroll
        for (int kb = 0; kb < 4; kb++) {
            int k8 = kb * 8;
            const float* a0p = As + (r0 + g4) * GA_STRIDE + k8 + q4;
            uint32_t a00 = __float_as_uint(a0p[0]);
            uint32_t a01 = __float_as_uint(a0p[8 * GA_STRIDE]);
            uint32_t a02 = __float_as_uint(a0p[4]);
            uint32_t a03 = __float_as_uint(a0p[8 * GA_STRIDE + 4]);
            uint32_t a10 = __float_as_uint(a0p[16 * GA_STRIDE]);
            uint32_t a11 = __float_as_uint(a0p[24 * GA_STRIDE]);
            uint32_t a12 = __float_as_uint(a0p[16 * GA_STRIDE + 4]);
            uint32_t a13 = __float_as_uint(a0p[24 * GA_STRIDE + 4]);
            const float* bp = Bs + (k8 + q4) * GB_STRIDE + c0 + g4;
#pragma unroll
            for (int nt = 0; nt < 4; nt++) {
                uint32_t b0 = __float_as_uint(bp[nt * 8]);
                uint32_t b1 = __float_as_uint(bp[nt * 8 + 4 * GB_STRIDE]);
                mma_tf32(acc[0][nt], a00, a01, a02, a03, b0, b1);
                mma_tf32(acc[1][nt], a10, a11, a12, a13, b0, b1);
            }
        }
    }
    // ---- C store ----
#pragma unroll
    for (int mt = 0; mt < 2; mt++) {
        int row = m0 + r0 + mt * 16 + g4;
        float* c0p = C + (size_t)row * 256 + n0 + c0;
        float* c1p = c0p + 8 * 256;
#pragma unroll
        for (int nt = 0; nt < 4; nt++) {
            int cc = nt * 8 + q4 * 2;
            float bx = 0.f, by = 0.f;
            if (BIAS) { bx = bias[n0 + c0 + cc]; by = bias[n0 + c0 + cc + 1]; }
            float2 u0, u1;
            u0.x = acc[mt][nt][0] + bx; u0.y = acc[mt][nt][1] + by;
            u1.x = acc[mt][nt][2] + bx; u1.y = acc[mt][nt][3] + by;
            *(float2*)(c0p + cc) = u0;
            *(float2*)(c1p + cc) = u1;
        }
    }
    // ---- fused a_src / a_dst (this block covers one full head's 64 cols) ----
    if (SAD) {
        float as_c[8], ad_c[8];
#pragma unroll
        for (int nt = 0; nt < 4; nt++) {
            int cg = n0 + c0 + nt * 8 + q4 * 2;
            as_c[nt * 2] = asrc[cg]; as_c[nt * 2 + 1] = asrc[cg + 1];
            ad_c[nt * 2] = adst[cg]; ad_c[nt * 2 + 1] = adst[cg + 1];
        }
        __syncthreads();                 // As no longer read; reuse as reduction buffer
        float* red = As;                 // [row][wn] float2 -> 128*2*2 floats
#pragma unroll
        for (int mt = 0; mt < 2; mt++) {
            float sAs = 0.f, sAd = 0.f, sBs = 0.f, sBd = 0.f;
#pragma unroll
            for (int nt = 0; nt < 4; nt++) {
                sAs += acc[mt][nt][0] * as_c[nt * 2] + acc[mt][nt][1] * as_c[nt * 2 + 1];
                sBs += acc[mt][nt][2] * as_c[nt * 2] + acc[mt][nt][3] * as_c[nt * 2 + 1];
                sAd += acc[mt][nt][0] * ad_c[nt * 2] + acc[mt][nt][1] * ad_c[nt * 2 + 1];
                sBd += acc[mt][nt][2] * ad_c[nt * 2] + acc[mt][nt][3] * ad_c[nt * 2 + 1];
            }
#pragma unroll
            for (int o = 1; o < 4; o <<= 1) {
                sAs += __shfl_xor_sync(0xffffffffu, sAs, o);
                sAd += __shfl_xor_sync(0xffffffffu, sAd, o);
                sBs += __shfl_xor_sync(0xffffffffu, sBs, o);
                sBd += __shfl_xor_sync(0xffffffffu, sBd, o);
            }
            if (q4 == 0) {
                int rA = r0 + mt * 16 + g4, rB = rA + 8;
                *(float2*)&red[(rA * 2 + wn) * 2] = make_float2(sAs, sAd);
                *(float2*)&red[(rB * 2 + wn) * 2] = make_float2(sBs, sBd);
            }
        }
        __syncthreads();
        if (tid < 128) {
            float2 v0 = *(float2*)&red[(tid * 2 + 0) * 2];
            float2 v1 = *(float2*)&red[(tid * 2 + 1) * 2];
            int b = m0 >> 10, n = (m0 & 1023) + tid;
            int bh = b * HEADS + blockIdx.y;
            g_as[bh * NNODE + n] = v0.x + v1.x;
            g_ad[bh * NNODE + n] = v0.y + v1.y;
        }
    }
}

__global__ __launch_bounds__(256) void asmax_kernel()
{
    int bh = blockIdx.x;
    __shared__ float sm[256];
    float m = -1e30f;
    for (int j = threadIdx.x; j < NNODE; j += 256) m = fmaxf(m, g_as[bh * NNODE + j]);
    sm[threadIdx.x] = m;
    __syncthreads();
    for (int o = 128; o; o >>= 1) {
        if (threadIdx.x < o) sm[threadIdx.x] = fmaxf(sm[threadIdx.x], sm[threadIdx.x + o]);
        __syncthreads();
    }
    if (threadIdx.x == 0) g_asmax[bh] = sm[0];
}

// ---------------- GAT attention: 256 rows/block, register-P tf32 mma.sync ----------
#define V_STRIDE 72
__global__ __launch_bounds__(256, 2) void gat_attn_mma(
    const float* __restrict__ wh, const float* __restrict__ gbias,
    float* __restrict__ hout)
{
    __shared__ float v_sm[64 * V_STRIDE];
    __shared__ float4 je[64];            // (as_j, E1_j, E2_j, -)
    __shared__ uint32_t adj_sm[512];

    int tid = threadIdx.x, w = tid >> 5, lane = tid & 31;
    int g4 = lane >> 2, q4 = lane & 3;
    int it = blockIdx.x, hh = blockIdx.y, b = blockIdx.z;
    int i0 = it * 256, bh = b * HEADS + hh;
    int r0 = w * 32;

    float F1[4], F2[4], adreg[4];
    {
        float mx = g_asmax[bh];
#pragma unroll
        for (int t = 0; t < 4; t++) {
            float ad = g_ad[bh * NNODE + i0 + r0 + t * 8 + g4];
            adreg[t] = ad;
            float mm = mx + ad;
            float mr = fmaxf(mm, 0.2f * mm);
            F1[t] = __expf(ad - mr);
            F2[t] = __expf(0.2f * ad - mr);
        }
    }
    // B cols 64..71: col 64 = ones (Z), rest zeros
#pragma unroll
    for (int q = 0; q < 2; q++) {
        int idx = q * 256 + tid;
        int jr = idx >> 3, cc = 64 + (idx & 7);
        v_sm[jr * V_STRIDE + cc] = (cc == 64) ? 1.f : 0.f;
    }

    float acc[2][9][4];
#pragma unroll
    for (int mt = 0; mt < 2; mt++)
#pragma unroll
        for (int n = 0; n < 9; n++)
#pragma unroll
            for (int k = 0; k < 4; k++) acc[mt][n][k] = 0.f;

    const float* whb = wh + ((size_t)(b * NNODE)) * DIM + hh * 64;
    const uint32_t* adjb = g_adjT + (size_t)b * 32 * NNODE + i0;

    for (int ch = 0; ch < 16; ch++) {
        int j0 = ch * 64;
        __syncthreads();
        // V chunk [64 x 64] -> v_sm (tf32-rounded), 4 float4 per thread
#pragma unroll
        for (int q = 0; q < 4; q++) {
            int idx = q * 256 + tid;
            int jr = idx >> 4, cc = (idx & 15) * 4;
            float4 v = *(const float4*)(whb + (size_t)(j0 + jr) * DIM + cc);
            float* dst = v_sm + jr * V_STRIDE + cc;
            dst[0] = __uint_as_float(tf32r(v.x));
            dst[1] = __uint_as_float(tf32r(v.y));
            dst[2] = __uint_as_float(tf32r(v.z));
            dst[3] = __uint_as_float(tf32r(v.w));
        }
        if (tid < 64) {
            float a = g_as[bh * NNODE + j0 + tid];
            je[tid] = make_float4(a, __expf(a), __expf(0.2f * a), 0.f);
        }
        adj_sm[tid] = adjb[(size_t)(2 * ch) * NNODE + tid];
        adj_sm[256 + tid] = adjb[(size_t)(2 * ch + 1) * NNODE + tid];
        __syncthreads();
        uint32_t Aw[2][4];
#pragma unroll
        for (int t = 0; t < 4; t++) {
            Aw[0][t] = adj_sm[r0 + t * 8 + g4];
            Aw[1][t] = adj_sm[256 + r0 + t * 8 + g4];
        }
#pragma unroll
        for (int kb = 0; kb < 8; kb++) {
            int jA = kb * 8 + q4;
            float4 jA4 = je[jA];
            float4 jB4 = je[jA + 4];
            int half = kb >> 2;
            int sh = jA & 31;
            uint32_t fr[2][4];
#pragma unroll
            for (int t = 0; t < 4; t++) {
                uint32_t Aword = Aw[half][t];
                uint32_t mA = (uint32_t)(((int32_t)(Aword << (31 - sh))) >> 31);
                uint32_t mB = (uint32_t)(((int32_t)(Aword << (27 - sh))) >> 31);
                float tA = jA4.x + adreg[t];
                float tB = jB4.x + adreg[t];
                float pA = (tA > 0.f) ? jA4.y * F1[t] : jA4.z * F2[t];
                float pB = (tB > 0.f) ? jB4.y * F1[t] : jB4.z * F2[t];
                fr[t >> 1][t & 1] = __float_as_uint(pA) & mA;
                fr[t >> 1][2 + (t & 1)] = __float_as_uint(pB) & mB;
            }
            const float* bp = v_sm + (kb * 8 + q4) * V_STRIDE + g4;
#pragma unroll
            for (int nt = 0; nt < 9; nt++) {
                uint32_t b0 = __float_as_uint(bp[nt * 8]);
                uint32_t b1 = __float_as_uint(bp[nt * 8 + 4 * V_STRIDE]);
                mma_tf32(acc[0][nt], fr[0][0], fr[0][1], fr[0][2], fr[0][3], b0, b1);
                mma_tf32(acc[1][nt], fr[1][0], fr[1][1], fr[1][2], fr[1][3], b0, b1);
            }
        }
    }
    const float* bp = gbias + hh * 64;
#pragma unroll
    for (int mt = 0; mt < 2; mt++) {
        float z0 = __shfl_sync(0xffffffffu, acc[mt][8][0], lane & 28);
        float z1 = __shfl_sync(0xffffffffu, acc[mt][8][2], lane & 28);
        float iz0 = 1.f / z0;
        float iz1 = 1.f / z1;
        int rowg = i0 + r0 + mt * 16 + g4;
        float* o0 = hout + ((size_t)(b * NNODE) + rowg) * DIM + hh * 64;
        float* o1 = o0 + 8 * DIM;
#pragma unroll
        for (int nt = 0; nt < 8; nt++) {
            int cc = nt * 8 + q4 * 2;
            float bx = bp[cc], by = bp[cc + 1];
            float2 u0, u1;
            u0.x = fmaxf(fmaf(acc[mt][nt][0], iz0, bx), 0.f);
            u0.y = fmaxf(fmaf(acc[mt][nt][1], iz0, by), 0.f);
            u1.x = fmaxf(fmaf(acc[mt][nt][2], iz1, bx), 0.f);
            u1.y = fmaxf(fmaf(acc[mt][nt][3], iz1, by), 0.f);
            *(float2*)(o0 + cc) = u0;
            *(float2*)(o1 + cc) = u1;
        }
    }
}

// ---------------- zero tail of output (mask = all false) ----------------
__global__ void zero_tail_kernel(float* out, long long start, long long total)
{
    long long i = start + (long long)blockIdx.x * blockDim.x + threadIdx.x;
    if (i < total) out[i] = 0.f;
}

// ---------------- launch ----------------
extern "C" void kernel_launch(void* const* d_in, const int* in_sizes, int n_in,
                              void* d_out, int out_size)
{
    const float* ego      = (const float*)d_in[0];
    const float* nbr      = (const float*)d_in[1];
    const float* node_w   = (const float*)d_in[2];
    const float* node_b   = (const float*)d_in[3];
    const float* node_g   = (const float*)d_in[4];
    const float* node_bb  = (const float*)d_in[5];
    const float* ego_w    = (const float*)d_in[6];
    const float* ego_b    = (const float*)d_in[7];
    const float* ego_g    = (const float*)d_in[8];
    const float* ego_bb   = (const float*)d_in[9];
    const float* gat_w    = (const float*)d_in[10];
    const float* gat_asrc = (const float*)d_in[11];
    const float* gat_adst = (const float*)d_in[12];
    const float* gat_b    = (const float*)d_in[13];
    const float* proj_w   = (const float*)d_in[14];
    const float* proj_b   = (const float*)d_in[15];
    float* out = (float*)d_out;

    float *h0, *h1, *wh;
    cudaGetSymbolAddress((void**)&h0, g_h0);
    cudaGetSymbolAddress((void**)&h1, g_h1);
    cudaGetSymbolAddress((void**)&wh, g_wh);

    embed_kernel<<<BATCH * NNODE / 8, 256>>>(ego, nbr, node_w, node_b, node_g, node_bb,
                                             ego_w, ego_b, ego_g, ego_bb);
    adj_kernel<<<dim3(NNODE / 32, 32, BATCH), 256>>>();

    long long hsz = (long long)BATCH * NNODE * DIM;
    if ((long long)out_size > hsz) {
        long long tail = (long long)out_size - hsz;
        int blocks = (int)((tail + 255) / 256);
        zero_tail_kernel<<<blocks, 256>>>(out, hsz, (long long)out_size);
    }

    dim3 ggrid(BATCH * NNODE / 128, 4);
    float* hbuf[2] = { h0, h1 };
    for (int l = 0; l < 2; l++) {
        tgemm256<false, true><<<ggrid, 256>>>(hbuf[l], gat_w + (long long)l * DIM * DIM,
                                              nullptr, wh,
                                              gat_asrc + l * HEADS * 64,
                                              gat_adst + l * HEADS * 64);
        asmax_kernel<<<BATCH * HEADS, 256>>>();
        gat_attn_mma<<<dim3(4, HEADS, BATCH), 256>>>(wh, gat_b + l * DIM, hbuf[1 - l]);
    }
    tgemm256<true, false><<<ggrid, 256>>>(h0, proj_w, proj_b, out, nullptr, nullptr);
}